// round 15
// baseline (speedup 1.0000x reference)
#include <cuda_runtime.h>
#include <math.h>

#define NNODE 20000
#define EEDGE 320000
#define CC 64
#define NBAS 8
#define NEL 4
#define GG 16
#define NL 9
#define HIDN 16
#define RMAXF 5.0f
#define PI_F 3.14159265358979f
#define NBLK 740
#define EBLK 444

// ---------------- device scratch ----------------
__device__ __align__(16) float d_hu0[NNODE * CC];
__device__ __align__(16) float d_Y[EEDGE * NL];
__device__ __align__(16) float d_ef[EEDGE * NBAS];
__device__ __align__(16) float d_u3[EEDGE * 3];
__device__ __align__(16) float d_r[EEDGE];
__device__ __align__(16) float d_R0[EEDGE * CC];
__device__ __align__(16) float d_R1[EEDGE * CC];
__device__ __align__(16) float d_hu1[NNODE * NL * CC];
__device__ __align__(16) float d_gagg1[NNODE * CC];
__device__ __align__(16) float d_gagg0[NNODE * NL * CC];
__device__ float d_contrib[GG * 3];
// CSR sort structures
__device__ int d_cnt_rcv[NNODE];
__device__ int d_cnt_snd[NNODE];
__device__ int d_off_rcv[NNODE + 1];
__device__ int d_off_snd[NNODE + 1];
__device__ int d_cur_rcv[NNODE];
__device__ int d_cur_snd[NNODE];
__device__ int d_eid_rcv[EEDGE];
__device__ int d_eid_snd[EEDGE];
// precomputed composites
__device__ float d_Wc[CC * CC];
__device__ float d_WcT[CC * CC];
__device__ float d_vread[CC];
__device__ float d_skup[NEL * CC];
__device__ float d_skrd[NEL];
__device__ float d_E0up[NEL * CC];

// ---------------- K0: zero ----------------
__global__ void k_zero(float* __restrict__ out, int out_size) {
    int idx = blockIdx.x * blockDim.x + threadIdx.x;
    if (idx < NNODE) { d_cnt_rcv[idx] = 0; d_cnt_snd[idx] = 0; }
    if (idx < (out_size + 3) / 4) {
        int b = idx * 4;
        #pragma unroll
        for (int k = 0; k < 4; k++) if (b + k < out_size) out[b + k] = 0.f;
    }
    if (idx < GG * 3) d_contrib[idx] = 0.f;
}

// ---------------- K hist / scan / fill: counting sort by rcv and snd ----------------
__global__ void k_hist(const int* __restrict__ eidx) {
    int e = blockIdx.x * blockDim.x + threadIdx.x;
    if (e < EEDGE) {
        atomicAdd(&d_cnt_snd[eidx[e]], 1);
        atomicAdd(&d_cnt_rcv[eidx[EEDGE + e]], 1);
    }
}

// one launch, two concurrent blocks: blockIdx 0 -> rcv, 1 -> snd
__global__ void k_scan2() {
    const int* cnt = blockIdx.x ? d_cnt_snd : d_cnt_rcv;
    int* off = blockIdx.x ? d_off_snd : d_off_rcv;
    int* cur = blockIdx.x ? d_cur_snd : d_cur_rcv;
    __shared__ int spart[1024];
    int t = threadIdx.x;
    const int CH = (NNODE + 1023) / 1024;
    int base = t * CH;
    int s = 0;
    for (int i = 0; i < CH; i++) {
        int idx = base + i;
        if (idx < NNODE) s += cnt[idx];
    }
    spart[t] = s;
    __syncthreads();
    for (int o = 1; o < 1024; o <<= 1) {
        int v = (t >= o) ? spart[t - o] : 0;
        __syncthreads();
        spart[t] += v;
        __syncthreads();
    }
    int excl = (t == 0) ? 0 : spart[t - 1];
    for (int i = 0; i < CH; i++) {
        int idx = base + i;
        if (idx < NNODE) {
            off[idx] = excl;
            cur[idx] = excl;
            excl += cnt[idx];
        }
    }
    if (t == 1023) off[NNODE] = excl;
}

__global__ void k_fill(const int* __restrict__ eidx) {
    int e = blockIdx.x * blockDim.x + threadIdx.x;
    if (e < EEDGE) {
        int p1 = atomicAdd(&d_cur_snd[eidx[e]], 1);
        d_eid_snd[p1] = e;
        int p2 = atomicAdd(&d_cur_rcv[eidx[EEDGE + e]], 1);
        d_eid_rcv[p2] = e;
    }
}

// ---------------- Kpre: composite weights ----------------
__global__ void k_pre(const float* __restrict__ W_embed, const float* __restrict__ W_up,
                      const float* __restrict__ W_out, const float* __restrict__ W_skip,
                      const float* __restrict__ w_read0) {
    int t = threadIdx.x;
    const float* Wup1 = W_up + CC * CC;
    for (int i = t; i < CC * CC; i += blockDim.x) {
        int c = i >> 6, d = i & 63;
        float acc = 0.f;
        #pragma unroll 8
        for (int k = 0; k < CC; k++) acc += W_out[c * CC + k] * Wup1[k * CC + d];
        d_Wc[i] = acc;
        d_WcT[d * CC + c] = acc;
    }
    for (int i = t; i < CC; i += blockDim.x) {
        float acc = 0.f;
        #pragma unroll 8
        for (int d = 0; d < CC; d++) acc += W_out[i * CC + d] * w_read0[d];
        d_vread[i] = acc;
    }
    for (int i = t; i < NEL * CC; i += blockDim.x) {
        int e = i >> 6, d = i & 63;
        float a = 0.f, b = 0.f;
        #pragma unroll 8
        for (int k = 0; k < CC; k++) {
            a += W_skip[e * CC + k] * Wup1[k * CC + d];
            b += W_embed[e * CC + k] * W_up[k * CC + d];
        }
        d_skup[i] = a;
        d_E0up[i] = b;
    }
    if (t < NEL) {
        float acc = 0.f;
        #pragma unroll 8
        for (int d = 0; d < CC; d++) acc += W_skip[t * CC + d] * w_read0[d];
        d_skrd[t] = acc;
    }
}

// ---------------- K1: node init ----------------
__global__ void k_node_init(const float* __restrict__ attrs, const float* __restrict__ ae,
                            const int* __restrict__ batch) {
    __shared__ float sE[NEL * CC];
    for (int i = threadIdx.x; i < NEL * CC; i += blockDim.x) sE[i] = d_E0up[i];
    __syncthreads();
    int warp = threadIdx.x >> 5, lane = threadIdx.x & 31;
    int n = blockIdx.x * 8 + warp;
    if (n >= NNODE) return;
    float a0 = attrs[n * 4 + 0], a1 = attrs[n * 4 + 1], a2 = attrs[n * 4 + 2], a3 = attrs[n * 4 + 3];
    #pragma unroll
    for (int k = 0; k < 2; k++) {
        int d = lane + 32 * k;
        d_hu0[n * CC + d] = a0 * sE[d] + a1 * sE[CC + d] + a2 * sE[2 * CC + d] + a3 * sE[3 * CC + d];
    }
    if (lane == 0) {
        float e0 = a0 * ae[0] + a1 * ae[1] + a2 * ae[2] + a3 * ae[3];
        atomicAdd(&d_contrib[batch[n] * 3 + 0], e0);
    }
}

// ---------------- K2: edge geometry + radial MLPs ----------------
__global__ void __launch_bounds__(256, 3)
k_edge_fwd(const float* __restrict__ pos, const float* __restrict__ shifts,
           const int* __restrict__ eidx,
           const float* __restrict__ W1, const float* __restrict__ W2) {
    __shared__ float sW1[2 * NBAS * CC];
    __shared__ float sW2[2 * CC * CC];
    __shared__ float sef[8][4][NBAS];
    __shared__ __align__(16) float sact[8][4][CC];
    for (int i = threadIdx.x; i < 2 * NBAS * CC; i += blockDim.x) sW1[i] = W1[i];
    for (int i = threadIdx.x; i < 2 * CC * CC; i += blockDim.x) sW2[i] = W2[i];
    __syncthreads();
    int warp = threadIdx.x >> 5, lane = threadIdx.x & 31;
    const float S3 = 1.7320508075688772f, S5 = 2.23606797749979f, S15 = 3.872983346207417f;
    for (int b = blockIdx.x * 8 + warp; b < EEDGE / 4; b += gridDim.x * 8) {
        int e0 = b * 4;
        if (lane < 4) {
            int e = e0 + lane;
            int snd = eidx[e], rcv = eidx[EEDGE + e];
            float vx = pos[snd * 3 + 0] - pos[rcv * 3 + 0] + shifts[e * 3 + 0];
            float vy = pos[snd * 3 + 1] - pos[rcv * 3 + 1] + shifts[e * 3 + 1];
            float vz = pos[snd * 3 + 2] - pos[rcv * 3 + 2] + shifts[e * 3 + 2];
            float r = sqrtf(vx * vx + vy * vy + vz * vz + 1e-12f);
            float inv = 1.0f / r;
            float x = vx * inv, y = vy * inv, z = vz * inv;
            float Yv[9];
            Yv[0] = 1.f; Yv[1] = S3 * x; Yv[2] = S3 * y; Yv[3] = S3 * z;
            Yv[4] = S15 * x * y; Yv[5] = S15 * y * z; Yv[6] = 0.5f * S5 * (3.f * z * z - 1.f);
            Yv[7] = S15 * x * z; Yv[8] = 0.5f * S15 * (x * x - y * y);
            float uu = r * (1.0f / RMAXF);
            float fc = 0.f;
            if (uu < 1.f) {
                float u2 = uu * uu, u4 = u2 * u2, u6 = u4 * u2, u7 = u6 * uu, u8 = u7 * uu;
                fc = 1.f - 28.f * u6 + 48.f * u7 - 21.f * u8;
            }
            const float A = 0.6324555320336759f;
            float th = r * (PI_F / RMAXF);
            float sb, cb;
            sincosf(th, &sb, &cb);
            float pref = A * inv * fc;
            float sn = sb, cn = cb;
            #pragma unroll
            for (int n = 0; n < NBAS; n++) {
                if (n > 0) {
                    float s2 = sn * cb + cn * sb;
                    float c2 = cn * cb - sn * sb;
                    sn = s2; cn = c2;
                }
                float efv = pref * sn;
                sef[warp][lane][n] = efv;
                d_ef[e * NBAS + n] = efv;
            }
            #pragma unroll
            for (int l = 0; l < 9; l++) d_Y[e * NL + l] = Yv[l];
            d_u3[e * 3 + 0] = x; d_u3[e * 3 + 1] = y; d_u3[e * 3 + 2] = z;
            d_r[e] = r;
        }
        __syncwarp();
        #pragma unroll
        for (int i = 0; i < 2; i++) {
            float z0[4] = {0.f, 0.f, 0.f, 0.f};
            float z1[4] = {0.f, 0.f, 0.f, 0.f};
            const float* w1 = &sW1[i * NBAS * CC];
            #pragma unroll
            for (int n = 0; n < NBAS; n++) {
                float wv0 = w1[n * CC + lane];
                float wv1 = w1[n * CC + lane + 32];
                #pragma unroll
                for (int e = 0; e < 4; e++) {
                    float efv = sef[warp][e][n];
                    z0[e] += efv * wv0;
                    z1[e] += efv * wv1;
                }
            }
            #pragma unroll
            for (int e = 0; e < 4; e++) {
                float sg0 = 1.f / (1.f + __expf(-z0[e]));
                float sg1 = 1.f / (1.f + __expf(-z1[e]));
                sact[warp][e][lane] = z0[e] * sg0;
                sact[warp][e][lane + 32] = z1[e] * sg1;
            }
            __syncwarp();
            float acc0[4] = {0.f, 0.f, 0.f, 0.f};
            float acc1[4] = {0.f, 0.f, 0.f, 0.f};
            const float* w2 = &sW2[i * CC * CC];
            #pragma unroll
            for (int c4 = 0; c4 < 16; c4++) {
                const float* w = &w2[c4 * 4 * CC + lane];
                float wA0 = w[0], wA1 = w[CC], wA2 = w[2 * CC], wA3 = w[3 * CC];
                float wB0 = w[32], wB1 = w[CC + 32], wB2 = w[2 * CC + 32], wB3 = w[3 * CC + 32];
                #pragma unroll
                for (int e = 0; e < 4; e++) {
                    float4 xv = ((const float4*)sact[warp][e])[c4];
                    acc0[e] += xv.x * wA0 + xv.y * wA1 + xv.z * wA2 + xv.w * wA3;
                    acc1[e] += xv.x * wB0 + xv.y * wB1 + xv.z * wB2 + xv.w * wB3;
                }
            }
            float* Rdst = i ? d_R1 : d_R0;
            #pragma unroll
            for (int e = 0; e < 4; e++) {
                int ee = e0 + e;
                Rdst[ee * CC + lane] = acc0[e];
                Rdst[ee * CC + lane + 32] = acc1[e];
            }
            __syncwarp();
        }
    }
}

// ---------------- K3: gather agg0 (rcv-CSR) + node update fused ----------------
__global__ void k_gather_upd(const float* __restrict__ attrs, const int* __restrict__ eidx,
                             const int* __restrict__ batch) {
    __shared__ float sWc[CC * CC];
    __shared__ float sku[NEL * CC];
    __shared__ float svr[CC];
    __shared__ float sskrd[NEL];
    __shared__ __align__(16) float scr[8][NL][CC];
    for (int i = threadIdx.x; i < CC * CC; i += blockDim.x) sWc[i] = d_Wc[i];
    for (int i = threadIdx.x; i < NEL * CC; i += blockDim.x) sku[i] = d_skup[i];
    for (int i = threadIdx.x; i < CC; i += blockDim.x) svr[i] = d_vread[i];
    if (threadIdx.x < NEL) sskrd[threadIdx.x] = d_skrd[threadIdx.x];
    __syncthreads();
    int warp = threadIdx.x >> 5, lane = threadIdx.x & 31;
    for (int n = blockIdx.x * 8 + warp; n < NNODE; n += gridDim.x * 8) {
        int beg = d_off_rcv[n], end = d_off_rcv[n + 1];
        float acc[NL][2];
        #pragma unroll
        for (int l = 0; l < NL; l++) { acc[l][0] = 0.f; acc[l][1] = 0.f; }
        for (int k = beg; k < end; k++) {
            int e = d_eid_rcv[k];
            int snd = eidx[e];
            float p0 = d_R0[e * CC + lane] * d_hu0[snd * CC + lane];
            float p1 = d_R0[e * CC + lane + 32] * d_hu0[snd * CC + lane + 32];
            #pragma unroll
            for (int l = 0; l < NL; l++) {
                float yl = d_Y[e * NL + l];
                acc[l][0] += yl * p0;
                acc[l][1] += yl * p1;
            }
        }
        float a0 = attrs[n * 4 + 0], a1 = attrs[n * 4 + 1], a2 = attrs[n * 4 + 2], a3 = attrs[n * 4 + 3];
        float ep = acc[0][0] * svr[lane] + acc[0][1] * svr[lane + 32];
        #pragma unroll
        for (int off = 16; off > 0; off >>= 1) ep += __shfl_xor_sync(0xffffffff, ep, off);
        if (lane == 0) {
            ep += a0 * sskrd[0] + a1 * sskrd[1] + a2 * sskrd[2] + a3 * sskrd[3];
            atomicAdd(&d_contrib[batch[n] * 3 + 1], ep);
        }
        #pragma unroll
        for (int l = 0; l < NL; l++) {
            scr[warp][l][lane] = acc[l][0];
            scr[warp][l][lane + 32] = acc[l][1];
        }
        __syncwarp();
        float o0[NL], o1[NL];
        #pragma unroll
        for (int l = 0; l < NL; l++) { o0[l] = 0.f; o1[l] = 0.f; }
        o0[0] = a0 * sku[lane] + a1 * sku[CC + lane] + a2 * sku[2 * CC + lane] + a3 * sku[3 * CC + lane];
        o1[0] = a0 * sku[lane + 32] + a1 * sku[CC + lane + 32] + a2 * sku[2 * CC + lane + 32] + a3 * sku[3 * CC + lane + 32];
        #pragma unroll
        for (int c4 = 0; c4 < 16; c4++) {
            const float* w = &sWc[(c4 * 4) * CC + lane];
            float wA0 = w[0], wA1 = w[CC], wA2 = w[2 * CC], wA3 = w[3 * CC];
            float wB0 = w[32], wB1 = w[CC + 32], wB2 = w[2 * CC + 32], wB3 = w[3 * CC + 32];
            #pragma unroll
            for (int l = 0; l < NL; l++) {
                float4 xv = ((const float4*)scr[warp][l])[c4];
                o0[l] += xv.x * wA0 + xv.y * wA1 + xv.z * wA2 + xv.w * wA3;
                o1[l] += xv.x * wB0 + xv.y * wB1 + xv.z * wB2 + xv.w * wB3;
            }
        }
        #pragma unroll
        for (int l = 0; l < NL; l++) {
            d_hu1[(n * NL + l) * CC + lane] = o0[l];
            d_hu1[(n * NL + l) * CC + lane + 32] = o1[l];
        }
        __syncwarp();
    }
}

// ---------------- K6: node2 with fused msg1 gather (rcv-CSR) ----------------
__global__ void k_node2(const float* __restrict__ attrs, const int* __restrict__ eidx,
                        const float* __restrict__ W_out1,
                        const float* __restrict__ W_skip1, const float* __restrict__ W_r1,
                        const float* __restrict__ w_r2, const int* __restrict__ batch) {
    __shared__ float sWo[CC * CC];
    __shared__ float sWoT[CC * CC];
    __shared__ float sWr[CC * 17];
    __shared__ float sr2[HIDN];
    __shared__ float sSk[NEL * CC];
    __shared__ __align__(16) float scr[8][CC];
    __shared__ float sgz[8][HIDN];
    for (int i = threadIdx.x; i < CC * CC; i += blockDim.x) {
        sWo[i] = W_out1[i];
        int d = i / CC, c = i % CC;
        sWoT[i] = W_out1[c * CC + d];
    }
    for (int i = threadIdx.x; i < CC * HIDN; i += blockDim.x) {
        int c = i / HIDN, h = i % HIDN;
        sWr[c * 17 + h] = W_r1[i];
    }
    for (int i = threadIdx.x; i < HIDN; i += blockDim.x) sr2[i] = w_r2[i];
    for (int i = threadIdx.x; i < NEL * CC; i += blockDim.x) sSk[i] = W_skip1[i];
    __syncthreads();
    int warp = threadIdx.x >> 5, lane = threadIdx.x & 31;
    for (int n = blockIdx.x * 8 + warp; n < NNODE; n += gridDim.x * 8) {
        // fused msg1: agg1[n] accumulated in registers over incoming edges
        float agg1a = 0.f, agg1b = 0.f;
        {
            int beg = d_off_rcv[n], end = d_off_rcv[n + 1];
            for (int k = beg; k < end; k++) {
                int e = d_eid_rcv[k];
                int snd = eidx[e];
                float Yv[9];
                #pragma unroll
                for (int l = 0; l < 9; l++) Yv[l] = d_Y[e * NL + l];
                float s0 = 0.f, s1 = 0.f;
                #pragma unroll
                for (int l = 0; l < 9; l++) {
                    s0 += d_hu1[(snd * NL + l) * CC + lane] * Yv[l];
                    s1 += d_hu1[(snd * NL + l) * CC + lane + 32] * Yv[l];
                }
                agg1a += d_R1[e * CC + lane] * s0;
                agg1b += d_R1[e * CC + lane + 32] * s1;
            }
        }
        scr[warp][lane] = agg1a;
        scr[warp][lane + 32] = agg1b;
        __syncwarp();
        float a0 = attrs[n * 4 + 0], a1 = attrs[n * 4 + 1], a2 = attrs[n * 4 + 2], a3 = attrs[n * 4 + 3];
        float h2a, h2b;
        {
            float acc0 = a0 * sSk[lane] + a1 * sSk[CC + lane] + a2 * sSk[2 * CC + lane] + a3 * sSk[3 * CC + lane];
            float acc1 = a0 * sSk[lane + 32] + a1 * sSk[CC + lane + 32] + a2 * sSk[2 * CC + lane + 32] + a3 * sSk[3 * CC + lane + 32];
            const float4* x4 = (const float4*)scr[warp];
            #pragma unroll
            for (int c4 = 0; c4 < 16; c4++) {
                float4 xv = x4[c4];
                const float* w = &sWo[(c4 * 4) * CC + lane];
                acc0 += xv.x * w[0] + xv.y * w[CC] + xv.z * w[2 * CC] + xv.w * w[3 * CC];
                acc1 += xv.x * w[32] + xv.y * w[CC + 32] + xv.z * w[2 * CC + 32] + xv.w * w[3 * CC + 32];
            }
            h2a = acc0; h2b = acc1;
        }
        __syncwarp();
        scr[warp][lane] = h2a; scr[warp][lane + 32] = h2b;
        __syncwarp();
        float ep = 0.f;
        if (lane < HIDN) {
            float zv = 0.f;
            #pragma unroll 8
            for (int d = 0; d < CC; d++) zv += scr[warp][d] * sWr[d * 17 + lane];
            float sg = 1.f / (1.f + __expf(-zv));
            ep = zv * sg * sr2[lane];
            sgz[warp][lane] = sg * (1.f + zv * (1.f - sg)) * sr2[lane];
        }
        #pragma unroll
        for (int off = 16; off > 0; off >>= 1) ep += __shfl_xor_sync(0xffffffff, ep, off);
        if (lane == 0) atomicAdd(&d_contrib[batch[n] * 3 + 2], ep);
        __syncwarp();
        float gh2a = 0.f, gh2b = 0.f;
        #pragma unroll
        for (int h = 0; h < HIDN; h++) {
            float g = sgz[warp][h];
            gh2a += g * sWr[lane * 17 + h];
            gh2b += g * sWr[(lane + 32) * 17 + h];
        }
        __syncwarp();
        scr[warp][lane] = gh2a; scr[warp][lane + 32] = gh2b;
        __syncwarp();
        {
            const float4* x4 = (const float4*)scr[warp];
            float acc0 = 0.f, acc1 = 0.f;
            #pragma unroll
            for (int c4 = 0; c4 < 16; c4++) {
                float4 xv = x4[c4];
                const float* w = &sWoT[(c4 * 4) * CC + lane];
                acc0 += xv.x * w[0] + xv.y * w[CC] + xv.z * w[2 * CC] + xv.w * w[3 * CC];
                acc1 += xv.x * w[32] + xv.y * w[CC + 32] + xv.z * w[2 * CC + 32] + xv.w * w[3 * CC + 32];
            }
            d_gagg1[n * CC + lane] = acc0;
            d_gagg1[n * CC + lane + 32] = acc1;
        }
        __syncwarp();
    }
}

// ---------------- K7: gather gagg0 (snd-CSR) + backward node fused ----------------
__global__ void k_back_gather(const int* __restrict__ eidx) {
    __shared__ float sWcT[CC * CC];
    __shared__ float svr[CC];
    __shared__ __align__(16) float scr[8][NL][CC];
    for (int i = threadIdx.x; i < CC * CC; i += blockDim.x) sWcT[i] = d_WcT[i];
    for (int i = threadIdx.x; i < CC; i += blockDim.x) svr[i] = d_vread[i];
    __syncthreads();
    int warp = threadIdx.x >> 5, lane = threadIdx.x & 31;
    for (int n = blockIdx.x * 8 + warp; n < NNODE; n += gridDim.x * 8) {
        int beg = d_off_snd[n], end = d_off_snd[n + 1];
        float acc[NL][2];
        #pragma unroll
        for (int l = 0; l < NL; l++) { acc[l][0] = 0.f; acc[l][1] = 0.f; }
        for (int k = beg; k < end; k++) {
            int e = d_eid_snd[k];
            int rcv = eidx[EEDGE + e];
            float q0 = d_R1[e * CC + lane] * d_gagg1[rcv * CC + lane];
            float q1 = d_R1[e * CC + lane + 32] * d_gagg1[rcv * CC + lane + 32];
            #pragma unroll
            for (int l = 0; l < NL; l++) {
                float yl = d_Y[e * NL + l];
                acc[l][0] += yl * q0;
                acc[l][1] += yl * q1;
            }
        }
        #pragma unroll
        for (int l = 0; l < NL; l++) {
            scr[warp][l][lane] = acc[l][0];
            scr[warp][l][lane + 32] = acc[l][1];
        }
        __syncwarp();
        float o0[NL], o1[NL];
        #pragma unroll
        for (int l = 0; l < NL; l++) { o0[l] = 0.f; o1[l] = 0.f; }
        o0[0] = svr[lane];
        o1[0] = svr[lane + 32];
        #pragma unroll
        for (int c4 = 0; c4 < 16; c4++) {
            const float* w = &sWcT[(c4 * 4) * CC + lane];
            float wA0 = w[0], wA1 = w[CC], wA2 = w[2 * CC], wA3 = w[3 * CC];
            float wB0 = w[32], wB1 = w[CC + 32], wB2 = w[2 * CC + 32], wB3 = w[3 * CC + 32];
            #pragma unroll
            for (int l = 0; l < NL; l++) {
                float4 xv = ((const float4*)scr[warp][l])[c4];
                o0[l] += xv.x * wA0 + xv.y * wA1 + xv.z * wA2 + xv.w * wA3;
                o1[l] += xv.x * wB0 + xv.y * wB1 + xv.z * wB2 + xv.w * wB3;
            }
        }
        #pragma unroll
        for (int l = 0; l < NL; l++) {
            d_gagg0[(n * NL + l) * CC + lane] = o0[l];
            d_gagg0[(n * NL + l) * CC + lane + 32] = o1[l];
        }
        __syncwarp();
    }
}

// ---------------- K9: backward edges -> forces, 4-edge batched ----------------
__global__ void __launch_bounds__(256, 2)
k_back_edge(const int* __restrict__ eidx,
            const float* __restrict__ W1, const float* __restrict__ W2,
            float* __restrict__ force) {
    __shared__ float sW2T[2][CC * CC];
    __shared__ float sW1p[2][NBAS * 65];
    __shared__ __align__(16) float sAB[8][4][CC];
    __shared__ float sef[8][4][NBAS];
    __shared__ float sgeo[8][4][4];
    for (int i = threadIdx.x; i < 2 * CC * CC; i += blockDim.x) {
        int w = i / (CC * CC), rem = i % (CC * CC);
        int c = rem / CC, j = rem % CC;
        sW2T[w][rem] = W2[w * CC * CC + j * CC + c];
    }
    for (int i = threadIdx.x; i < 2 * NBAS * CC; i += blockDim.x) {
        int w = i / (NBAS * CC), rem = i % (NBAS * CC);
        int n = rem / CC, j = rem % CC;
        sW1p[w][n * 65 + j] = W1[i];
    }
    __syncthreads();
    int warp = threadIdx.x >> 5, lane = threadIdx.x & 31;
    const float S3 = 1.7320508075688772f, S5 = 2.23606797749979f, S15 = 3.872983346207417f;
    for (int b = blockIdx.x * 8 + warp; b < EEDGE / 4; b += gridDim.x * 8) {
        int e0 = b * 4;
        float pX[4], pY[4], pZ[4];
        float gR1a[4], gR1b[4];
        int snds[4], rcvs[4];
        #pragma unroll
        for (int e = 0; e < 4; e++) {
            int ee = e0 + e;
            int snd = eidx[ee], rcv = eidx[EEDGE + ee];
            snds[e] = snd; rcvs[e] = rcv;
            float Yv[9];
            #pragma unroll
            for (int l = 0; l < 9; l++) Yv[l] = d_Y[ee * NL + l];
            float ux = d_u3[ee * 3], uy = d_u3[ee * 3 + 1], uz = d_u3[ee * 3 + 2];
            if (lane == 0) {
                sgeo[warp][e][0] = ux; sgeo[warp][e][1] = uy; sgeo[warp][e][2] = uz;
                sgeo[warp][e][3] = d_r[ee];
            }
            if (lane < NBAS) sef[warp][e][lane] = d_ef[ee * NBAS + lane];
            float cx[9] = {0.f, S3, 0.f, 0.f, S15 * uy, 0.f, 0.f, S15 * uz, S15 * ux};
            float cy[9] = {0.f, 0.f, S3, 0.f, S15 * ux, S15 * uz, 0.f, 0.f, -S15 * uy};
            float cz[9] = {0.f, 0.f, 0.f, S3, 0.f, S15 * uy, 3.f * S5 * uz, S15 * ux, 0.f};
            float g0 = d_gagg1[rcv * CC + lane], g1 = d_gagg1[rcv * CC + lane + 32];
            float R1a = d_R1[ee * CC + lane], R1b = d_R1[ee * CC + lane + 32];
            float gs1a = R1a * g0, gs1b = R1b * g1;
            float s0a = d_hu0[snd * CC + lane], s0b = d_hu0[snd * CC + lane + 32];
            float p0a = d_R0[ee * CC + lane] * s0a, p0b = d_R0[ee * CC + lane + 32] * s0b;
            float t0a = 0.f, t0b = 0.f, s1a = 0.f, s1b = 0.f;
            float px = 0.f, py = 0.f, pz = 0.f;
            #pragma unroll
            for (int l = 0; l < 9; l++) {
                float ga = d_gagg0[(rcv * NL + l) * CC + lane];
                float gb = d_gagg0[(rcv * NL + l) * CC + lane + 32];
                float ha = d_hu1[(snd * NL + l) * CC + lane];
                float hb = d_hu1[(snd * NL + l) * CC + lane + 32];
                t0a += Yv[l] * ga; t0b += Yv[l] * gb;
                s1a += ha * Yv[l]; s1b += hb * Yv[l];
                if (l > 0) {
                    float part = p0a * ga + p0b * gb + ha * gs1a + hb * gs1b;
                    px += cx[l] * part;
                    py += cy[l] * part;
                    pz += cz[l] * part;
                }
            }
            sAB[warp][e][lane] = t0a * s0a;
            sAB[warp][e][lane + 32] = t0b * s0b;
            gR1a[e] = s1a * g0; gR1b[e] = s1b * g1;
            pX[e] = px; pY[e] = py; pZ[e] = pz;
        }
        __syncwarp();
        float gefl = 0.f;
        int eg = lane >> 3, nb = lane & 7;
        #pragma unroll
        for (int i = 0; i < 2; i++) {
            if (i == 1) {
                __syncwarp();
                #pragma unroll
                for (int e = 0; e < 4; e++) {
                    sAB[warp][e][lane] = gR1a[e];
                    sAB[warp][e][lane + 32] = gR1b[e];
                }
                __syncwarp();
            }
            float gz0[4] = {0.f, 0.f, 0.f, 0.f};
            float gz1[4] = {0.f, 0.f, 0.f, 0.f};
            #pragma unroll
            for (int c4 = 0; c4 < 16; c4++) {
                const float* w = &sW2T[i][(c4 * 4) * CC + lane];
                float wA0 = w[0], wA1 = w[CC], wA2 = w[2 * CC], wA3 = w[3 * CC];
                float wB0 = w[32], wB1 = w[CC + 32], wB2 = w[2 * CC + 32], wB3 = w[3 * CC + 32];
                #pragma unroll
                for (int e = 0; e < 4; e++) {
                    float4 xv = ((const float4*)sAB[warp][e])[c4];
                    gz0[e] += xv.x * wA0 + xv.y * wA1 + xv.z * wA2 + xv.w * wA3;
                    gz1[e] += xv.x * wB0 + xv.y * wB1 + xv.z * wB2 + xv.w * wB3;
                }
            }
            float pre0[4] = {0.f, 0.f, 0.f, 0.f};
            float pre1[4] = {0.f, 0.f, 0.f, 0.f};
            #pragma unroll
            for (int n = 0; n < NBAS; n++) {
                float wv0 = sW1p[i][n * 65 + lane];
                float wv1 = sW1p[i][n * 65 + lane + 32];
                #pragma unroll
                for (int e = 0; e < 4; e++) {
                    float efv = sef[warp][e][n];
                    pre0[e] += efv * wv0;
                    pre1[e] += efv * wv1;
                }
            }
            __syncwarp();
            #pragma unroll
            for (int e = 0; e < 4; e++) {
                float sg0 = 1.f / (1.f + __expf(-pre0[e]));
                float sg1 = 1.f / (1.f + __expf(-pre1[e]));
                sAB[warp][e][lane] = gz0[e] * sg0 * (1.f + pre0[e] * (1.f - sg0));
                sAB[warp][e][lane + 32] = gz1[e] * sg1 * (1.f + pre1[e] * (1.f - sg1));
            }
            __syncwarp();
            float acc = 0.f;
            #pragma unroll 8
            for (int j = 0; j < CC; j++)
                acc += sAB[warp][eg][j] * sW1p[i][nb * 65 + j];
            gefl += acc;
        }
        float grp;
        {
            float r_e = sgeo[warp][eg][3];
            float kn = (nb + 1) * (PI_F / RMAXF);
            float invr = 1.f / r_e;
            const float A = 0.6324555320336759f;
            float sn, cs;
            sincosf(kn * r_e, &sn, &cs);
            float uu = r_e * (1.0f / RMAXF);
            float fc = 0.f, dfc = 0.f;
            if (uu < 1.f) {
                float u2 = uu * uu, u4 = u2 * u2, u5 = u4 * uu, u6 = u5 * uu, u7 = u6 * uu;
                fc = 1.f - 28.f * u6 + 48.f * u7 - 21.f * u7 * uu;
                dfc = (-168.f * u5 + 336.f * u6 - 168.f * u7) * (1.0f / RMAXF);
            }
            float rb = A * sn * invr;
            float drb = A * (kn * cs - sn * invr) * invr;
            grp = gefl * (drb * fc + rb * dfc);
        }
        #pragma unroll
        for (int off = 4; off > 0; off >>= 1) grp += __shfl_xor_sync(0xffffffff, grp, off);
        #pragma unroll
        for (int e = 0; e < 4; e++) {
            #pragma unroll
            for (int off = 16; off > 0; off >>= 1) {
                pX[e] += __shfl_xor_sync(0xffffffff, pX[e], off);
                pY[e] += __shfl_xor_sync(0xffffffff, pY[e], off);
                pZ[e] += __shfl_xor_sync(0xffffffff, pZ[e], off);
            }
        }
        if ((lane & 7) == 0) {
            int e = eg;
            float px = (e == 0) ? pX[0] : (e == 1) ? pX[1] : (e == 2) ? pX[2] : pX[3];
            float py = (e == 0) ? pY[0] : (e == 1) ? pY[1] : (e == 2) ? pY[2] : pY[3];
            float pz = (e == 0) ? pZ[0] : (e == 1) ? pZ[1] : (e == 2) ? pZ[2] : pZ[3];
            int snd = (e == 0) ? snds[0] : (e == 1) ? snds[1] : (e == 2) ? snds[2] : snds[3];
            int rcv = (e == 0) ? rcvs[0] : (e == 1) ? rcvs[1] : (e == 2) ? rcvs[2] : rcvs[3];
            float ux = sgeo[warp][e][0], uy = sgeo[warp][e][1], uz = sgeo[warp][e][2];
            float invr = 1.f / sgeo[warp][e][3];
            if (snd != rcv) {
                float dot = px * ux + py * uy + pz * uz;
                float gvx = (px - dot * ux) * invr + grp * ux;
                float gvy = (py - dot * uy) * invr + grp * uy;
                float gvz = (pz - dot * uz) * invr + grp * uz;
                atomicAdd(&force[snd * 3 + 0], -gvx);
                atomicAdd(&force[snd * 3 + 1], -gvy);
                atomicAdd(&force[snd * 3 + 2], -gvz);
                atomicAdd(&force[rcv * 3 + 0], gvx);
                atomicAdd(&force[rcv * 3 + 1], gvy);
                atomicAdd(&force[rcv * 3 + 2], gvz);
            }
        }
    }
}

// ---------------- K10: finalize ----------------
__global__ void k_final(float* __restrict__ out) {
    int g = threadIdx.x;
    if (g < GG) {
        float c0 = d_contrib[g * 3 + 0], c1 = d_contrib[g * 3 + 1], c2 = d_contrib[g * 3 + 2];
        out[g] = c0 + c1 + c2;
        out[GG + g * 3 + 0] = c0;
        out[GG + g * 3 + 1] = c1;
        out[GG + g * 3 + 2] = c2;
    }
}

extern "C" void kernel_launch(void* const* d_in, const int* in_sizes, int n_in,
                              void* d_out, int out_size) {
    const float* pos     = (const float*)d_in[0];
    const float* attrs   = (const float*)d_in[1];
    const float* shifts  = (const float*)d_in[2];
    const float* ae      = (const float*)d_in[3];
    const float* W_embed = (const float*)d_in[4];
    const float* W_up    = (const float*)d_in[5];
    const float* W1      = (const float*)d_in[6];
    const float* W2      = (const float*)d_in[7];
    const float* W_out   = (const float*)d_in[8];
    const float* W_skip  = (const float*)d_in[9];
    const float* w_read0 = (const float*)d_in[10];
    const float* W_r1    = (const float*)d_in[11];
    const float* w_r2    = (const float*)d_in[12];
    const int*   eidx    = (const int*)d_in[13];
    const int*   batch   = (const int*)d_in[14];
    float* out = (float*)d_out;

    k_zero<<<(NNODE + 255) / 256, 256>>>(out, out_size);
    k_pre<<<1, 256>>>(W_embed, W_up, W_out, W_skip, w_read0);
    k_hist<<<(EEDGE + 255) / 256, 256>>>(eidx);
    k_scan2<<<2, 1024>>>();
    k_fill<<<(EEDGE + 255) / 256, 256>>>(eidx);
    k_node_init<<<(NNODE + 7) / 8, 256>>>(attrs, ae, batch);
    k_edge_fwd<<<EBLK, 256>>>(pos, shifts, eidx, W1, W2);
    k_gather_upd<<<NBLK, 256>>>(attrs, eidx, batch);
    k_node2<<<NBLK, 256>>>(attrs, eidx, W_out + CC * CC, W_skip + NEL * CC, W_r1, w_r2, batch);
    k_back_gather<<<NBLK, 256>>>(eidx);
    k_back_edge<<<NBLK, 256>>>(eidx, W1, W2, out + GG + GG * 3);
    k_final<<<1, 64>>>(out);
}

// round 16
// speedup vs baseline: 1.0458x; 1.0458x over previous
#include <cuda_runtime.h>
#include <math.h>

#define NNODE 20000
#define EEDGE 320000
#define CC 64
#define NBAS 8
#define NEL 4
#define GG 16
#define NL 9
#define HIDN 16
#define RMAXF 5.0f
#define PI_F 3.14159265358979f
#define NBLK 740
#define EBLK 444

// ---------------- device scratch ----------------
__device__ __align__(16) float d_hu0[NNODE * CC];
__device__ __align__(16) float d_Y[EEDGE * NL];
__device__ __align__(16) float d_ef[EEDGE * NBAS];
__device__ __align__(16) float d_u3[EEDGE * 3];
__device__ __align__(16) float d_r[EEDGE];
__device__ __align__(16) float d_R0[EEDGE * CC];
__device__ __align__(16) float d_R1[EEDGE * CC];
__device__ __align__(16) float d_hu1[NNODE * NL * CC];
__device__ __align__(16) float d_agg1[NNODE * CC];
__device__ __align__(16) float d_gagg1[NNODE * CC];
__device__ __align__(16) float d_gagg0[NNODE * NL * CC];
__device__ float d_contrib[GG * 3];
// CSR sort structures
__device__ int d_cnt_rcv[NNODE];
__device__ int d_cnt_snd[NNODE];
__device__ int d_off_rcv[NNODE + 1];
__device__ int d_off_snd[NNODE + 1];
__device__ int d_cur_rcv[NNODE];
__device__ int d_cur_snd[NNODE];
__device__ int d_eid_rcv[EEDGE];
__device__ int d_eid_snd[EEDGE];
// precomputed composites
__device__ float d_Wc[CC * CC];
__device__ float d_WcT[CC * CC];
__device__ float d_vread[CC];
__device__ float d_skup[NEL * CC];
__device__ float d_skrd[NEL];
__device__ float d_E0up[NEL * CC];

// ---------------- K0: zero ----------------
__global__ void k_zero(float* __restrict__ out, int out_size) {
    int idx = blockIdx.x * blockDim.x + threadIdx.x;
    const float4 z4 = make_float4(0.f, 0.f, 0.f, 0.f);
    if (idx < NNODE * CC / 4) ((float4*)d_agg1)[idx] = z4;
    if (idx < NNODE) { d_cnt_rcv[idx] = 0; d_cnt_snd[idx] = 0; }
    if (idx < (out_size + 3) / 4) {
        int b = idx * 4;
        #pragma unroll
        for (int k = 0; k < 4; k++) if (b + k < out_size) out[b + k] = 0.f;
    }
    if (idx < GG * 3) d_contrib[idx] = 0.f;
}

// ---------------- K hist / scan / fill: counting sort by rcv and snd ----------------
__global__ void k_hist(const int* __restrict__ eidx) {
    int e = blockIdx.x * blockDim.x + threadIdx.x;
    if (e < EEDGE) {
        atomicAdd(&d_cnt_snd[eidx[e]], 1);
        atomicAdd(&d_cnt_rcv[eidx[EEDGE + e]], 1);
    }
}

// one launch, two concurrent blocks: blockIdx 0 -> rcv, 1 -> snd
__global__ void k_scan2() {
    const int* cnt = blockIdx.x ? d_cnt_snd : d_cnt_rcv;
    int* off = blockIdx.x ? d_off_snd : d_off_rcv;
    int* cur = blockIdx.x ? d_cur_snd : d_cur_rcv;
    __shared__ int spart[1024];
    int t = threadIdx.x;
    const int CH = (NNODE + 1023) / 1024;
    int base = t * CH;
    int s = 0;
    for (int i = 0; i < CH; i++) {
        int idx = base + i;
        if (idx < NNODE) s += cnt[idx];
    }
    spart[t] = s;
    __syncthreads();
    for (int o = 1; o < 1024; o <<= 1) {
        int v = (t >= o) ? spart[t - o] : 0;
        __syncthreads();
        spart[t] += v;
        __syncthreads();
    }
    int excl = (t == 0) ? 0 : spart[t - 1];
    for (int i = 0; i < CH; i++) {
        int idx = base + i;
        if (idx < NNODE) {
            off[idx] = excl;
            cur[idx] = excl;
            excl += cnt[idx];
        }
    }
    if (t == 1023) off[NNODE] = excl;
}

__global__ void k_fill(const int* __restrict__ eidx) {
    int e = blockIdx.x * blockDim.x + threadIdx.x;
    if (e < EEDGE) {
        int p1 = atomicAdd(&d_cur_snd[eidx[e]], 1);
        d_eid_snd[p1] = e;
        int p2 = atomicAdd(&d_cur_rcv[eidx[EEDGE + e]], 1);
        d_eid_rcv[p2] = e;
    }
}

// ---------------- Kpre: composite weights ----------------
__global__ void k_pre(const float* __restrict__ W_embed, const float* __restrict__ W_up,
                      const float* __restrict__ W_out, const float* __restrict__ W_skip,
                      const float* __restrict__ w_read0) {
    int t = threadIdx.x;
    const float* Wup1 = W_up + CC * CC;
    for (int i = t; i < CC * CC; i += blockDim.x) {
        int c = i >> 6, d = i & 63;
        float acc = 0.f;
        #pragma unroll 8
        for (int k = 0; k < CC; k++) acc += W_out[c * CC + k] * Wup1[k * CC + d];
        d_Wc[i] = acc;
        d_WcT[d * CC + c] = acc;
    }
    for (int i = t; i < CC; i += blockDim.x) {
        float acc = 0.f;
        #pragma unroll 8
        for (int d = 0; d < CC; d++) acc += W_out[i * CC + d] * w_read0[d];
        d_vread[i] = acc;
    }
    for (int i = t; i < NEL * CC; i += blockDim.x) {
        int e = i >> 6, d = i & 63;
        float a = 0.f, b = 0.f;
        #pragma unroll 8
        for (int k = 0; k < CC; k++) {
            a += W_skip[e * CC + k] * Wup1[k * CC + d];
            b += W_embed[e * CC + k] * W_up[k * CC + d];
        }
        d_skup[i] = a;
        d_E0up[i] = b;
    }
    if (t < NEL) {
        float acc = 0.f;
        #pragma unroll 8
        for (int d = 0; d < CC; d++) acc += W_skip[t * CC + d] * w_read0[d];
        d_skrd[t] = acc;
    }
}

// ---------------- K1: node init ----------------
__global__ void k_node_init(const float* __restrict__ attrs, const float* __restrict__ ae,
                            const int* __restrict__ batch) {
    __shared__ float sE[NEL * CC];
    for (int i = threadIdx.x; i < NEL * CC; i += blockDim.x) sE[i] = d_E0up[i];
    __syncthreads();
    int warp = threadIdx.x >> 5, lane = threadIdx.x & 31;
    int n = blockIdx.x * 8 + warp;
    if (n >= NNODE) return;
    float a0 = attrs[n * 4 + 0], a1 = attrs[n * 4 + 1], a2 = attrs[n * 4 + 2], a3 = attrs[n * 4 + 3];
    #pragma unroll
    for (int k = 0; k < 2; k++) {
        int d = lane + 32 * k;
        d_hu0[n * CC + d] = a0 * sE[d] + a1 * sE[CC + d] + a2 * sE[2 * CC + d] + a3 * sE[3 * CC + d];
    }
    if (lane == 0) {
        float e0 = a0 * ae[0] + a1 * ae[1] + a2 * ae[2] + a3 * ae[3];
        atomicAdd(&d_contrib[batch[n] * 3 + 0], e0);
    }
}

// ---------------- K2: edge geometry + radial MLPs ----------------
__global__ void __launch_bounds__(256, 3)
k_edge_fwd(const float* __restrict__ pos, const float* __restrict__ shifts,
           const int* __restrict__ eidx,
           const float* __restrict__ W1, const float* __restrict__ W2) {
    __shared__ float sW1[2 * NBAS * CC];
    __shared__ float sW2[2 * CC * CC];
    __shared__ float sef[8][4][NBAS];
    __shared__ __align__(16) float sact[8][4][CC];
    for (int i = threadIdx.x; i < 2 * NBAS * CC; i += blockDim.x) sW1[i] = W1[i];
    for (int i = threadIdx.x; i < 2 * CC * CC; i += blockDim.x) sW2[i] = W2[i];
    __syncthreads();
    int warp = threadIdx.x >> 5, lane = threadIdx.x & 31;
    const float S3 = 1.7320508075688772f, S5 = 2.23606797749979f, S15 = 3.872983346207417f;
    for (int b = blockIdx.x * 8 + warp; b < EEDGE / 4; b += gridDim.x * 8) {
        int e0 = b * 4;
        if (lane < 4) {
            int e = e0 + lane;
            int snd = eidx[e], rcv = eidx[EEDGE + e];
            float vx = pos[snd * 3 + 0] - pos[rcv * 3 + 0] + shifts[e * 3 + 0];
            float vy = pos[snd * 3 + 1] - pos[rcv * 3 + 1] + shifts[e * 3 + 1];
            float vz = pos[snd * 3 + 2] - pos[rcv * 3 + 2] + shifts[e * 3 + 2];
            float r = sqrtf(vx * vx + vy * vy + vz * vz + 1e-12f);
            float inv = 1.0f / r;
            float x = vx * inv, y = vy * inv, z = vz * inv;
            float Yv[9];
            Yv[0] = 1.f; Yv[1] = S3 * x; Yv[2] = S3 * y; Yv[3] = S3 * z;
            Yv[4] = S15 * x * y; Yv[5] = S15 * y * z; Yv[6] = 0.5f * S5 * (3.f * z * z - 1.f);
            Yv[7] = S15 * x * z; Yv[8] = 0.5f * S15 * (x * x - y * y);
            float uu = r * (1.0f / RMAXF);
            float fc = 0.f;
            if (uu < 1.f) {
                float u2 = uu * uu, u4 = u2 * u2, u6 = u4 * u2, u7 = u6 * uu, u8 = u7 * uu;
                fc = 1.f - 28.f * u6 + 48.f * u7 - 21.f * u8;
            }
            const float A = 0.6324555320336759f;
            float th = r * (PI_F / RMAXF);
            float sb, cb;
            sincosf(th, &sb, &cb);
            float pref = A * inv * fc;
            float sn = sb, cn = cb;
            #pragma unroll
            for (int n = 0; n < NBAS; n++) {
                if (n > 0) {
                    float s2 = sn * cb + cn * sb;
                    float c2 = cn * cb - sn * sb;
                    sn = s2; cn = c2;
                }
                float efv = pref * sn;
                sef[warp][lane][n] = efv;
                d_ef[e * NBAS + n] = efv;
            }
            #pragma unroll
            for (int l = 0; l < 9; l++) d_Y[e * NL + l] = Yv[l];
            d_u3[e * 3 + 0] = x; d_u3[e * 3 + 1] = y; d_u3[e * 3 + 2] = z;
            d_r[e] = r;
        }
        __syncwarp();
        #pragma unroll
        for (int i = 0; i < 2; i++) {
            float z0[4] = {0.f, 0.f, 0.f, 0.f};
            float z1[4] = {0.f, 0.f, 0.f, 0.f};
            const float* w1 = &sW1[i * NBAS * CC];
            #pragma unroll
            for (int n = 0; n < NBAS; n++) {
                float wv0 = w1[n * CC + lane];
                float wv1 = w1[n * CC + lane + 32];
                #pragma unroll
                for (int e = 0; e < 4; e++) {
                    float efv = sef[warp][e][n];
                    z0[e] += efv * wv0;
                    z1[e] += efv * wv1;
                }
            }
            #pragma unroll
            for (int e = 0; e < 4; e++) {
                float sg0 = 1.f / (1.f + __expf(-z0[e]));
                float sg1 = 1.f / (1.f + __expf(-z1[e]));
                sact[warp][e][lane] = z0[e] * sg0;
                sact[warp][e][lane + 32] = z1[e] * sg1;
            }
            __syncwarp();
            float acc0[4] = {0.f, 0.f, 0.f, 0.f};
            float acc1[4] = {0.f, 0.f, 0.f, 0.f};
            const float* w2 = &sW2[i * CC * CC];
            #pragma unroll
            for (int c4 = 0; c4 < 16; c4++) {
                const float* w = &w2[c4 * 4 * CC + lane];
                float wA0 = w[0], wA1 = w[CC], wA2 = w[2 * CC], wA3 = w[3 * CC];
                float wB0 = w[32], wB1 = w[CC + 32], wB2 = w[2 * CC + 32], wB3 = w[3 * CC + 32];
                #pragma unroll
                for (int e = 0; e < 4; e++) {
                    float4 xv = ((const float4*)sact[warp][e])[c4];
                    acc0[e] += xv.x * wA0 + xv.y * wA1 + xv.z * wA2 + xv.w * wA3;
                    acc1[e] += xv.x * wB0 + xv.y * wB1 + xv.z * wB2 + xv.w * wB3;
                }
            }
            float* Rdst = i ? d_R1 : d_R0;
            #pragma unroll
            for (int e = 0; e < 4; e++) {
                int ee = e0 + e;
                Rdst[ee * CC + lane] = acc0[e];
                Rdst[ee * CC + lane + 32] = acc1[e];
            }
            __syncwarp();
        }
    }
}

// ---------------- K3: gather agg0 (rcv-CSR) + node update fused ----------------
__global__ void k_gather_upd(const float* __restrict__ attrs, const int* __restrict__ eidx,
                             const int* __restrict__ batch) {
    __shared__ float sWc[CC * CC];
    __shared__ float sku[NEL * CC];
    __shared__ float svr[CC];
    __shared__ float sskrd[NEL];
    __shared__ __align__(16) float scr[8][NL][CC];
    for (int i = threadIdx.x; i < CC * CC; i += blockDim.x) sWc[i] = d_Wc[i];
    for (int i = threadIdx.x; i < NEL * CC; i += blockDim.x) sku[i] = d_skup[i];
    for (int i = threadIdx.x; i < CC; i += blockDim.x) svr[i] = d_vread[i];
    if (threadIdx.x < NEL) sskrd[threadIdx.x] = d_skrd[threadIdx.x];
    __syncthreads();
    int warp = threadIdx.x >> 5, lane = threadIdx.x & 31;
    for (int n = blockIdx.x * 8 + warp; n < NNODE; n += gridDim.x * 8) {
        int beg = d_off_rcv[n], end = d_off_rcv[n + 1];
        float acc[NL][2];
        #pragma unroll
        for (int l = 0; l < NL; l++) { acc[l][0] = 0.f; acc[l][1] = 0.f; }
        for (int k = beg; k < end; k++) {
            int e = d_eid_rcv[k];
            int snd = eidx[e];
            float p0 = d_R0[e * CC + lane] * d_hu0[snd * CC + lane];
            float p1 = d_R0[e * CC + lane + 32] * d_hu0[snd * CC + lane + 32];
            #pragma unroll
            for (int l = 0; l < NL; l++) {
                float yl = d_Y[e * NL + l];
                acc[l][0] += yl * p0;
                acc[l][1] += yl * p1;
            }
        }
        float a0 = attrs[n * 4 + 0], a1 = attrs[n * 4 + 1], a2 = attrs[n * 4 + 2], a3 = attrs[n * 4 + 3];
        float ep = acc[0][0] * svr[lane] + acc[0][1] * svr[lane + 32];
        #pragma unroll
        for (int off = 16; off > 0; off >>= 1) ep += __shfl_xor_sync(0xffffffff, ep, off);
        if (lane == 0) {
            ep += a0 * sskrd[0] + a1 * sskrd[1] + a2 * sskrd[2] + a3 * sskrd[3];
            atomicAdd(&d_contrib[batch[n] * 3 + 1], ep);
        }
        #pragma unroll
        for (int l = 0; l < NL; l++) {
            scr[warp][l][lane] = acc[l][0];
            scr[warp][l][lane + 32] = acc[l][1];
        }
        __syncwarp();
        float o0[NL], o1[NL];
        #pragma unroll
        for (int l = 0; l < NL; l++) { o0[l] = 0.f; o1[l] = 0.f; }
        o0[0] = a0 * sku[lane] + a1 * sku[CC + lane] + a2 * sku[2 * CC + lane] + a3 * sku[3 * CC + lane];
        o1[0] = a0 * sku[lane + 32] + a1 * sku[CC + lane + 32] + a2 * sku[2 * CC + lane + 32] + a3 * sku[3 * CC + lane + 32];
        #pragma unroll
        for (int c4 = 0; c4 < 16; c4++) {
            const float* w = &sWc[(c4 * 4) * CC + lane];
            float wA0 = w[0], wA1 = w[CC], wA2 = w[2 * CC], wA3 = w[3 * CC];
            float wB0 = w[32], wB1 = w[CC + 32], wB2 = w[2 * CC + 32], wB3 = w[3 * CC + 32];
            #pragma unroll
            for (int l = 0; l < NL; l++) {
                float4 xv = ((const float4*)scr[warp][l])[c4];
                o0[l] += xv.x * wA0 + xv.y * wA1 + xv.z * wA2 + xv.w * wA3;
                o1[l] += xv.x * wB0 + xv.y * wB1 + xv.z * wB2 + xv.w * wB3;
            }
        }
        #pragma unroll
        for (int l = 0; l < NL; l++) {
            d_hu1[(n * NL + l) * CC + lane] = o0[l];
            d_hu1[(n * NL + l) * CC + lane + 32] = o1[l];
        }
        __syncwarp();
    }
}

// ---------------- K5: forward edge iter1 (warp-per-edge, scalar atomics) ----------------
__global__ void k_msg1(const int* __restrict__ eidx) {
    int warp = threadIdx.x >> 5, lane = threadIdx.x & 31;
    int e = blockIdx.x * 8 + warp;
    if (e >= EEDGE) return;
    int snd = eidx[e], rcv = eidx[EEDGE + e];
    float Yv[9];
    #pragma unroll
    for (int l = 0; l < 9; l++) Yv[l] = d_Y[e * NL + l];
    #pragma unroll
    for (int k = 0; k < 2; k++) {
        int c = lane + 32 * k;
        float s = 0.f;
        #pragma unroll
        for (int l = 0; l < 9; l++) s += d_hu1[(snd * NL + l) * CC + c] * Yv[l];
        atomicAdd(&d_agg1[rcv * CC + c], d_R1[e * CC + c] * s);
    }
}

// ---------------- K6: node2 (reads agg1) ----------------
__global__ void k_node2(const float* __restrict__ attrs, const float* __restrict__ W_out1,
                        const float* __restrict__ W_skip1, const float* __restrict__ W_r1,
                        const float* __restrict__ w_r2, const int* __restrict__ batch) {
    __shared__ float sWo[CC * CC];
    __shared__ float sWoT[CC * CC];
    __shared__ float sWr[CC * 17];
    __shared__ float sr2[HIDN];
    __shared__ float sSk[NEL * CC];
    __shared__ __align__(16) float scr[8][CC];
    __shared__ float sgz[8][HIDN];
    for (int i = threadIdx.x; i < CC * CC; i += blockDim.x) {
        sWo[i] = W_out1[i];
        int d = i / CC, c = i % CC;
        sWoT[i] = W_out1[c * CC + d];
    }
    for (int i = threadIdx.x; i < CC * HIDN; i += blockDim.x) {
        int c = i / HIDN, h = i % HIDN;
        sWr[c * 17 + h] = W_r1[i];
    }
    for (int i = threadIdx.x; i < HIDN; i += blockDim.x) sr2[i] = w_r2[i];
    for (int i = threadIdx.x; i < NEL * CC; i += blockDim.x) sSk[i] = W_skip1[i];
    __syncthreads();
    int warp = threadIdx.x >> 5, lane = threadIdx.x & 31;
    for (int n = blockIdx.x * 8 + warp; n < NNODE; n += gridDim.x * 8) {
        float4* s4 = (float4*)scr[warp];
        if (lane < 16) s4[lane] = ((const float4*)&d_agg1[n * CC])[lane];
        __syncwarp();
        float a0 = attrs[n * 4 + 0], a1 = attrs[n * 4 + 1], a2 = attrs[n * 4 + 2], a3 = attrs[n * 4 + 3];
        float h2a, h2b;
        {
            float acc0 = a0 * sSk[lane] + a1 * sSk[CC + lane] + a2 * sSk[2 * CC + lane] + a3 * sSk[3 * CC + lane];
            float acc1 = a0 * sSk[lane + 32] + a1 * sSk[CC + lane + 32] + a2 * sSk[2 * CC + lane + 32] + a3 * sSk[3 * CC + lane + 32];
            const float4* x4 = (const float4*)scr[warp];
            #pragma unroll
            for (int c4 = 0; c4 < 16; c4++) {
                float4 xv = x4[c4];
                const float* w = &sWo[(c4 * 4) * CC + lane];
                acc0 += xv.x * w[0] + xv.y * w[CC] + xv.z * w[2 * CC] + xv.w * w[3 * CC];
                acc1 += xv.x * w[32] + xv.y * w[CC + 32] + xv.z * w[2 * CC + 32] + xv.w * w[3 * CC + 32];
            }
            h2a = acc0; h2b = acc1;
        }
        __syncwarp();
        scr[warp][lane] = h2a; scr[warp][lane + 32] = h2b;
        __syncwarp();
        float ep = 0.f;
        if (lane < HIDN) {
            float zv = 0.f;
            #pragma unroll 8
            for (int d = 0; d < CC; d++) zv += scr[warp][d] * sWr[d * 17 + lane];
            float sg = 1.f / (1.f + __expf(-zv));
            ep = zv * sg * sr2[lane];
            sgz[warp][lane] = sg * (1.f + zv * (1.f - sg)) * sr2[lane];
        }
        #pragma unroll
        for (int off = 16; off > 0; off >>= 1) ep += __shfl_xor_sync(0xffffffff, ep, off);
        if (lane == 0) atomicAdd(&d_contrib[batch[n] * 3 + 2], ep);
        __syncwarp();
        float gh2a = 0.f, gh2b = 0.f;
        #pragma unroll
        for (int h = 0; h < HIDN; h++) {
            float g = sgz[warp][h];
            gh2a += g * sWr[lane * 17 + h];
            gh2b += g * sWr[(lane + 32) * 17 + h];
        }
        __syncwarp();
        scr[warp][lane] = gh2a; scr[warp][lane + 32] = gh2b;
        __syncwarp();
        {
            const float4* x4 = (const float4*)scr[warp];
            float acc0 = 0.f, acc1 = 0.f;
            #pragma unroll
            for (int c4 = 0; c4 < 16; c4++) {
                float4 xv = x4[c4];
                const float* w = &sWoT[(c4 * 4) * CC + lane];
                acc0 += xv.x * w[0] + xv.y * w[CC] + xv.z * w[2 * CC] + xv.w * w[3 * CC];
                acc1 += xv.x * w[32] + xv.y * w[CC + 32] + xv.z * w[2 * CC + 32] + xv.w * w[3 * CC + 32];
            }
            d_gagg1[n * CC + lane] = acc0;
            d_gagg1[n * CC + lane + 32] = acc1;
        }
        __syncwarp();
    }
}

// ---------------- K7: gather gagg0 (snd-CSR) + backward node fused ----------------
__global__ void k_back_gather(const int* __restrict__ eidx) {
    __shared__ float sWcT[CC * CC];
    __shared__ float svr[CC];
    __shared__ __align__(16) float scr[8][NL][CC];
    for (int i = threadIdx.x; i < CC * CC; i += blockDim.x) sWcT[i] = d_WcT[i];
    for (int i = threadIdx.x; i < CC; i += blockDim.x) svr[i] = d_vread[i];
    __syncthreads();
    int warp = threadIdx.x >> 5, lane = threadIdx.x & 31;
    for (int n = blockIdx.x * 8 + warp; n < NNODE; n += gridDim.x * 8) {
        int beg = d_off_snd[n], end = d_off_snd[n + 1];
        float acc[NL][2];
        #pragma unroll
        for (int l = 0; l < NL; l++) { acc[l][0] = 0.f; acc[l][1] = 0.f; }
        for (int k = beg; k < end; k++) {
            int e = d_eid_snd[k];
            int rcv = eidx[EEDGE + e];
            float q0 = d_R1[e * CC + lane] * d_gagg1[rcv * CC + lane];
            float q1 = d_R1[e * CC + lane + 32] * d_gagg1[rcv * CC + lane + 32];
            #pragma unroll
            for (int l = 0; l < NL; l++) {
                float yl = d_Y[e * NL + l];
                acc[l][0] += yl * q0;
                acc[l][1] += yl * q1;
            }
        }
        #pragma unroll
        for (int l = 0; l < NL; l++) {
            scr[warp][l][lane] = acc[l][0];
            scr[warp][l][lane + 32] = acc[l][1];
        }
        __syncwarp();
        float o0[NL], o1[NL];
        #pragma unroll
        for (int l = 0; l < NL; l++) { o0[l] = 0.f; o1[l] = 0.f; }
        o0[0] = svr[lane];
        o1[0] = svr[lane + 32];
        #pragma unroll
        for (int c4 = 0; c4 < 16; c4++) {
            const float* w = &sWcT[(c4 * 4) * CC + lane];
            float wA0 = w[0], wA1 = w[CC], wA2 = w[2 * CC], wA3 = w[3 * CC];
            float wB0 = w[32], wB1 = w[CC + 32], wB2 = w[2 * CC + 32], wB3 = w[3 * CC + 32];
            #pragma unroll
            for (int l = 0; l < NL; l++) {
                float4 xv = ((const float4*)scr[warp][l])[c4];
                o0[l] += xv.x * wA0 + xv.y * wA1 + xv.z * wA2 + xv.w * wA3;
                o1[l] += xv.x * wB0 + xv.y * wB1 + xv.z * wB2 + xv.w * wB3;
            }
        }
        #pragma unroll
        for (int l = 0; l < NL; l++) {
            d_gagg0[(n * NL + l) * CC + lane] = o0[l];
            d_gagg0[(n * NL + l) * CC + lane + 32] = o1[l];
        }
        __syncwarp();
    }
}

// ---------------- K9: backward edges -> forces, 4-edge batched ----------------
__global__ void __launch_bounds__(256, 2)
k_back_edge(const int* __restrict__ eidx,
            const float* __restrict__ W1, const float* __restrict__ W2,
            float* __restrict__ force) {
    __shared__ float sW2T[2][CC * CC];
    __shared__ float sW1p[2][NBAS * 65];
    __shared__ __align__(16) float sAB[8][4][CC];
    __shared__ float sef[8][4][NBAS];
    __shared__ float sgeo[8][4][4];
    for (int i = threadIdx.x; i < 2 * CC * CC; i += blockDim.x) {
        int w = i / (CC * CC), rem = i % (CC * CC);
        int c = rem / CC, j = rem % CC;
        sW2T[w][rem] = W2[w * CC * CC + j * CC + c];
    }
    for (int i = threadIdx.x; i < 2 * NBAS * CC; i += blockDim.x) {
        int w = i / (NBAS * CC), rem = i % (NBAS * CC);
        int n = rem / CC, j = rem % CC;
        sW1p[w][n * 65 + j] = W1[i];
    }
    __syncthreads();
    int warp = threadIdx.x >> 5, lane = threadIdx.x & 31;
    const float S3 = 1.7320508075688772f, S5 = 2.23606797749979f, S15 = 3.872983346207417f;
    for (int b = blockIdx.x * 8 + warp; b < EEDGE / 4; b += gridDim.x * 8) {
        int e0 = b * 4;
        float pX[4], pY[4], pZ[4];
        float gR1a[4], gR1b[4];
        int snds[4], rcvs[4];
        #pragma unroll
        for (int e = 0; e < 4; e++) {
            int ee = e0 + e;
            int snd = eidx[ee], rcv = eidx[EEDGE + ee];
            snds[e] = snd; rcvs[e] = rcv;
            float Yv[9];
            #pragma unroll
            for (int l = 0; l < 9; l++) Yv[l] = d_Y[ee * NL + l];
            float ux = d_u3[ee * 3], uy = d_u3[ee * 3 + 1], uz = d_u3[ee * 3 + 2];
            if (lane == 0) {
                sgeo[warp][e][0] = ux; sgeo[warp][e][1] = uy; sgeo[warp][e][2] = uz;
                sgeo[warp][e][3] = d_r[ee];
            }
            if (lane < NBAS) sef[warp][e][lane] = d_ef[ee * NBAS + lane];
            float cx[9] = {0.f, S3, 0.f, 0.f, S15 * uy, 0.f, 0.f, S15 * uz, S15 * ux};
            float cy[9] = {0.f, 0.f, S3, 0.f, S15 * ux, S15 * uz, 0.f, 0.f, -S15 * uy};
            float cz[9] = {0.f, 0.f, 0.f, S3, 0.f, S15 * uy, 3.f * S5 * uz, S15 * ux, 0.f};
            float g0 = d_gagg1[rcv * CC + lane], g1 = d_gagg1[rcv * CC + lane + 32];
            float R1a = d_R1[ee * CC + lane], R1b = d_R1[ee * CC + lane + 32];
            float gs1a = R1a * g0, gs1b = R1b * g1;
            float s0a = d_hu0[snd * CC + lane], s0b = d_hu0[snd * CC + lane + 32];
            float p0a = d_R0[ee * CC + lane] * s0a, p0b = d_R0[ee * CC + lane + 32] * s0b;
            float t0a = 0.f, t0b = 0.f, s1a = 0.f, s1b = 0.f;
            float px = 0.f, py = 0.f, pz = 0.f;
            #pragma unroll
            for (int l = 0; l < 9; l++) {
                float ga = d_gagg0[(rcv * NL + l) * CC + lane];
                float gb = d_gagg0[(rcv * NL + l) * CC + lane + 32];
                float ha = d_hu1[(snd * NL + l) * CC + lane];
                float hb = d_hu1[(snd * NL + l) * CC + lane + 32];
                t0a += Yv[l] * ga; t0b += Yv[l] * gb;
                s1a += ha * Yv[l]; s1b += hb * Yv[l];
                if (l > 0) {
                    float part = p0a * ga + p0b * gb + ha * gs1a + hb * gs1b;
                    px += cx[l] * part;
                    py += cy[l] * part;
                    pz += cz[l] * part;
                }
            }
            sAB[warp][e][lane] = t0a * s0a;
            sAB[warp][e][lane + 32] = t0b * s0b;
            gR1a[e] = s1a * g0; gR1b[e] = s1b * g1;
            pX[e] = px; pY[e] = py; pZ[e] = pz;
        }
        __syncwarp();
        float gefl = 0.f;
        int eg = lane >> 3, nb = lane & 7;
        #pragma unroll
        for (int i = 0; i < 2; i++) {
            if (i == 1) {
                __syncwarp();
                #pragma unroll
                for (int e = 0; e < 4; e++) {
                    sAB[warp][e][lane] = gR1a[e];
                    sAB[warp][e][lane + 32] = gR1b[e];
                }
                __syncwarp();
            }
            float gz0[4] = {0.f, 0.f, 0.f, 0.f};
            float gz1[4] = {0.f, 0.f, 0.f, 0.f};
            #pragma unroll
            for (int c4 = 0; c4 < 16; c4++) {
                const float* w = &sW2T[i][(c4 * 4) * CC + lane];
                float wA0 = w[0], wA1 = w[CC], wA2 = w[2 * CC], wA3 = w[3 * CC];
                float wB0 = w[32], wB1 = w[CC + 32], wB2 = w[2 * CC + 32], wB3 = w[3 * CC + 32];
                #pragma unroll
                for (int e = 0; e < 4; e++) {
                    float4 xv = ((const float4*)sAB[warp][e])[c4];
                    gz0[e] += xv.x * wA0 + xv.y * wA1 + xv.z * wA2 + xv.w * wA3;
                    gz1[e] += xv.x * wB0 + xv.y * wB1 + xv.z * wB2 + xv.w * wB3;
                }
            }
            float pre0[4] = {0.f, 0.f, 0.f, 0.f};
            float pre1[4] = {0.f, 0.f, 0.f, 0.f};
            #pragma unroll
            for (int n = 0; n < NBAS; n++) {
                float wv0 = sW1p[i][n * 65 + lane];
                float wv1 = sW1p[i][n * 65 + lane + 32];
                #pragma unroll
                for (int e = 0; e < 4; e++) {
                    float efv = sef[warp][e][n];
                    pre0[e] += efv * wv0;
                    pre1[e] += efv * wv1;
                }
            }
            __syncwarp();
            #pragma unroll
            for (int e = 0; e < 4; e++) {
                float sg0 = 1.f / (1.f + __expf(-pre0[e]));
                float sg1 = 1.f / (1.f + __expf(-pre1[e]));
                sAB[warp][e][lane] = gz0[e] * sg0 * (1.f + pre0[e] * (1.f - sg0));
                sAB[warp][e][lane + 32] = gz1[e] * sg1 * (1.f + pre1[e] * (1.f - sg1));
            }
            __syncwarp();
            float acc = 0.f;
            #pragma unroll 8
            for (int j = 0; j < CC; j++)
                acc += sAB[warp][eg][j] * sW1p[i][nb * 65 + j];
            gefl += acc;
        }
        float grp;
        {
            float r_e = sgeo[warp][eg][3];
            float kn = (nb + 1) * (PI_F / RMAXF);
            float invr = 1.f / r_e;
            const float A = 0.6324555320336759f;
            float sn, cs;
            sincosf(kn * r_e, &sn, &cs);
            float uu = r_e * (1.0f / RMAXF);
            float fc = 0.f, dfc = 0.f;
            if (uu < 1.f) {
                float u2 = uu * uu, u4 = u2 * u2, u5 = u4 * uu, u6 = u5 * uu, u7 = u6 * uu;
                fc = 1.f - 28.f * u6 + 48.f * u7 - 21.f * u7 * uu;
                dfc = (-168.f * u5 + 336.f * u6 - 168.f * u7) * (1.0f / RMAXF);
            }
            float rb = A * sn * invr;
            float drb = A * (kn * cs - sn * invr) * invr;
            grp = gefl * (drb * fc + rb * dfc);
        }
        #pragma unroll
        for (int off = 4; off > 0; off >>= 1) grp += __shfl_xor_sync(0xffffffff, grp, off);
        #pragma unroll
        for (int e = 0; e < 4; e++) {
            #pragma unroll
            for (int off = 16; off > 0; off >>= 1) {
                pX[e] += __shfl_xor_sync(0xffffffff, pX[e], off);
                pY[e] += __shfl_xor_sync(0xffffffff, pY[e], off);
                pZ[e] += __shfl_xor_sync(0xffffffff, pZ[e], off);
            }
        }
        if ((lane & 7) == 0) {
            int e = eg;
            float px = (e == 0) ? pX[0] : (e == 1) ? pX[1] : (e == 2) ? pX[2] : pX[3];
            float py = (e == 0) ? pY[0] : (e == 1) ? pY[1] : (e == 2) ? pY[2] : pY[3];
            float pz = (e == 0) ? pZ[0] : (e == 1) ? pZ[1] : (e == 2) ? pZ[2] : pZ[3];
            int snd = (e == 0) ? snds[0] : (e == 1) ? snds[1] : (e == 2) ? snds[2] : snds[3];
            int rcv = (e == 0) ? rcvs[0] : (e == 1) ? rcvs[1] : (e == 2) ? rcvs[2] : rcvs[3];
            float ux = sgeo[warp][e][0], uy = sgeo[warp][e][1], uz = sgeo[warp][e][2];
            float invr = 1.f / sgeo[warp][e][3];
            if (snd != rcv) {
                float dot = px * ux + py * uy + pz * uz;
                float gvx = (px - dot * ux) * invr + grp * ux;
                float gvy = (py - dot * uy) * invr + grp * uy;
                float gvz = (pz - dot * uz) * invr + grp * uz;
                atomicAdd(&force[snd * 3 + 0], -gvx);
                atomicAdd(&force[snd * 3 + 1], -gvy);
                atomicAdd(&force[snd * 3 + 2], -gvz);
                atomicAdd(&force[rcv * 3 + 0], gvx);
                atomicAdd(&force[rcv * 3 + 1], gvy);
                atomicAdd(&force[rcv * 3 + 2], gvz);
            }
        }
    }
}

// ---------------- K10: finalize ----------------
__global__ void k_final(float* __restrict__ out) {
    int g = threadIdx.x;
    if (g < GG) {
        float c0 = d_contrib[g * 3 + 0], c1 = d_contrib[g * 3 + 1], c2 = d_contrib[g * 3 + 2];
        out[g] = c0 + c1 + c2;
        out[GG + g * 3 + 0] = c0;
        out[GG + g * 3 + 1] = c1;
        out[GG + g * 3 + 2] = c2;
    }
}

extern "C" void kernel_launch(void* const* d_in, const int* in_sizes, int n_in,
                              void* d_out, int out_size) {
    const float* pos     = (const float*)d_in[0];
    const float* attrs   = (const float*)d_in[1];
    const float* shifts  = (const float*)d_in[2];
    const float* ae      = (const float*)d_in[3];
    const float* W_embed = (const float*)d_in[4];
    const float* W_up    = (const float*)d_in[5];
    const float* W1      = (const float*)d_in[6];
    const float* W2      = (const float*)d_in[7];
    const float* W_out   = (const float*)d_in[8];
    const float* W_skip  = (const float*)d_in[9];
    const float* w_read0 = (const float*)d_in[10];
    const float* W_r1    = (const float*)d_in[11];
    const float* w_r2    = (const float*)d_in[12];
    const int*   eidx    = (const int*)d_in[13];
    const int*   batch   = (const int*)d_in[14];
    float* out = (float*)d_out;

    k_zero<<<(NNODE * CC / 4 + 255) / 256, 256>>>(out, out_size);
    k_pre<<<1, 256>>>(W_embed, W_up, W_out, W_skip, w_read0);
    k_hist<<<(EEDGE + 255) / 256, 256>>>(eidx);
    k_scan2<<<2, 1024>>>();
    k_fill<<<(EEDGE + 255) / 256, 256>>>(eidx);
    k_node_init<<<(NNODE + 7) / 8, 256>>>(attrs, ae, batch);
    k_edge_fwd<<<EBLK, 256>>>(pos, shifts, eidx, W1, W2);
    k_gather_upd<<<NBLK, 256>>>(attrs, eidx, batch);
    k_msg1<<<(EEDGE + 7) / 8, 256>>>(eidx);
    k_node2<<<NBLK, 256>>>(attrs, W_out + CC * CC, W_skip + NEL * CC, W_r1, w_r2, batch);
    k_back_gather<<<NBLK, 256>>>(eidx);
    k_back_edge<<<NBLK, 256>>>(eidx, W1, W2, out + GG + GG * 3);
    k_final<<<1, 64>>>(out);
}

// round 17
// speedup vs baseline: 1.0598x; 1.0134x over previous
#include <cuda_runtime.h>
#include <math.h>

#define NNODE 20000
#define EEDGE 320000
#define CC 64
#define NBAS 8
#define NEL 4
#define GG 16
#define NL 9
#define HIDN 16
#define RMAXF 5.0f
#define PI_F 3.14159265358979f
#define NBLK 740
#define EBLK 444

// ---------------- device scratch ----------------
__device__ __align__(16) float d_hu0[NNODE * CC];
__device__ __align__(16) float d_Y[EEDGE * NL];
__device__ __align__(16) float d_ef[EEDGE * NBAS];
__device__ __align__(16) float d_u3[EEDGE * 3];
__device__ __align__(16) float d_r[EEDGE];
__device__ __align__(16) float d_R0[EEDGE * CC];
__device__ __align__(16) float d_R1[EEDGE * CC];
__device__ __align__(16) float d_hu1[NNODE * NL * CC];
__device__ __align__(16) float d_agg1[NNODE * CC];
__device__ __align__(16) float d_gagg1[NNODE * CC];
__device__ __align__(16) float d_gagg0[NNODE * NL * CC];
__device__ float d_contrib[GG * 3];
// CSR sort structures
__device__ int d_cnt_rcv[NNODE];
__device__ int d_cnt_snd[NNODE];
__device__ int d_off_rcv[NNODE + 1];
__device__ int d_off_snd[NNODE + 1];
__device__ int d_cur_rcv[NNODE];
__device__ int d_cur_snd[NNODE];
__device__ int d_eid_rcv[EEDGE];
__device__ int d_eid_snd[EEDGE];
// precomputed composites
__device__ float d_Wc[CC * CC];
__device__ float d_WcT[CC * CC];
__device__ float d_vread[CC];
__device__ float d_skup[NEL * CC];
__device__ float d_skrd[NEL];
__device__ float d_E0up[NEL * CC];

// ---------------- K0: zero ----------------
__global__ void k_zero(float* __restrict__ out, int out_size) {
    int idx = blockIdx.x * blockDim.x + threadIdx.x;
    const float4 z4 = make_float4(0.f, 0.f, 0.f, 0.f);
    if (idx < NNODE * CC / 4) ((float4*)d_agg1)[idx] = z4;
    if (idx < NNODE) { d_cnt_rcv[idx] = 0; d_cnt_snd[idx] = 0; }
    if (idx < (out_size + 3) / 4) {
        int b = idx * 4;
        #pragma unroll
        for (int k = 0; k < 4; k++) if (b + k < out_size) out[b + k] = 0.f;
    }
    if (idx < GG * 3) d_contrib[idx] = 0.f;
}

// ---------------- K hist / scan / fill: counting sort by rcv and snd ----------------
__global__ void k_hist(const int* __restrict__ eidx) {
    int e = blockIdx.x * blockDim.x + threadIdx.x;
    if (e < EEDGE) {
        atomicAdd(&d_cnt_snd[eidx[e]], 1);
        atomicAdd(&d_cnt_rcv[eidx[EEDGE + e]], 1);
    }
}

// one launch, two concurrent blocks: blockIdx 0 -> rcv, 1 -> snd
// two-level warp-shuffle scan (2 syncthreads total)
__global__ void k_scan2() {
    const int* cnt = blockIdx.x ? d_cnt_snd : d_cnt_rcv;
    int* off = blockIdx.x ? d_off_snd : d_off_rcv;
    int* cur = blockIdx.x ? d_cur_snd : d_cur_rcv;
    __shared__ int wsum[32];
    int t = threadIdx.x, lane = t & 31, wid = t >> 5;
    const int CH = (NNODE + 1023) / 1024;
    int base = t * CH;
    int s = 0;
    for (int i = 0; i < CH; i++) {
        int idx = base + i;
        if (idx < NNODE) s += cnt[idx];
    }
    int own = s;
    #pragma unroll
    for (int o = 1; o < 32; o <<= 1) {
        int v = __shfl_up_sync(0xffffffff, s, o);
        if (lane >= o) s += v;
    }
    if (lane == 31) wsum[wid] = s;
    __syncthreads();
    if (wid == 0) {
        int w = wsum[lane];
        #pragma unroll
        for (int o = 1; o < 32; o <<= 1) {
            int v = __shfl_up_sync(0xffffffff, w, o);
            if (lane >= o) w += v;
        }
        wsum[lane] = w;
    }
    __syncthreads();
    int excl = (wid > 0 ? wsum[wid - 1] : 0) + s - own;
    for (int i = 0; i < CH; i++) {
        int idx = base + i;
        if (idx < NNODE) {
            off[idx] = excl;
            cur[idx] = excl;
            excl += cnt[idx];
        }
    }
    if (t == 1023) off[NNODE] = wsum[31];
}

__global__ void k_fill(const int* __restrict__ eidx) {
    int e = blockIdx.x * blockDim.x + threadIdx.x;
    if (e < EEDGE) {
        int p1 = atomicAdd(&d_cur_snd[eidx[e]], 1);
        d_eid_snd[p1] = e;
        int p2 = atomicAdd(&d_cur_rcv[eidx[EEDGE + e]], 1);
        d_eid_rcv[p2] = e;
    }
}

// ---------------- Kpre: composite weights ----------------
__global__ void k_pre(const float* __restrict__ W_embed, const float* __restrict__ W_up,
                      const float* __restrict__ W_out, const float* __restrict__ W_skip,
                      const float* __restrict__ w_read0) {
    int t = threadIdx.x;
    const float* Wup1 = W_up + CC * CC;
    for (int i = t; i < CC * CC; i += blockDim.x) {
        int c = i >> 6, d = i & 63;
        float acc = 0.f;
        #pragma unroll 8
        for (int k = 0; k < CC; k++) acc += W_out[c * CC + k] * Wup1[k * CC + d];
        d_Wc[i] = acc;
        d_WcT[d * CC + c] = acc;
    }
    for (int i = t; i < CC; i += blockDim.x) {
        float acc = 0.f;
        #pragma unroll 8
        for (int d = 0; d < CC; d++) acc += W_out[i * CC + d] * w_read0[d];
        d_vread[i] = acc;
    }
    for (int i = t; i < NEL * CC; i += blockDim.x) {
        int e = i >> 6, d = i & 63;
        float a = 0.f, b = 0.f;
        #pragma unroll 8
        for (int k = 0; k < CC; k++) {
            a += W_skip[e * CC + k] * Wup1[k * CC + d];
            b += W_embed[e * CC + k] * W_up[k * CC + d];
        }
        d_skup[i] = a;
        d_E0up[i] = b;
    }
    if (t < NEL) {
        float acc = 0.f;
        #pragma unroll 8
        for (int d = 0; d < CC; d++) acc += W_skip[t * CC + d] * w_read0[d];
        d_skrd[t] = acc;
    }
}

// ---------------- K1: node init ----------------
__global__ void k_node_init(const float* __restrict__ attrs, const float* __restrict__ ae,
                            const int* __restrict__ batch) {
    __shared__ float sE[NEL * CC];
    for (int i = threadIdx.x; i < NEL * CC; i += blockDim.x) sE[i] = d_E0up[i];
    __syncthreads();
    int warp = threadIdx.x >> 5, lane = threadIdx.x & 31;
    int n = blockIdx.x * 8 + warp;
    if (n >= NNODE) return;
    float a0 = attrs[n * 4 + 0], a1 = attrs[n * 4 + 1], a2 = attrs[n * 4 + 2], a3 = attrs[n * 4 + 3];
    #pragma unroll
    for (int k = 0; k < 2; k++) {
        int d = lane + 32 * k;
        d_hu0[n * CC + d] = a0 * sE[d] + a1 * sE[CC + d] + a2 * sE[2 * CC + d] + a3 * sE[3 * CC + d];
    }
    if (lane == 0) {
        float e0 = a0 * ae[0] + a1 * ae[1] + a2 * ae[2] + a3 * ae[3];
        atomicAdd(&d_contrib[batch[n] * 3 + 0], e0);
    }
}

// ---------------- K2: edge geometry + radial MLPs ----------------
__global__ void __launch_bounds__(256, 3)
k_edge_fwd(const float* __restrict__ pos, const float* __restrict__ shifts,
           const int* __restrict__ eidx,
           const float* __restrict__ W1, const float* __restrict__ W2) {
    __shared__ float sW1[2 * NBAS * CC];
    __shared__ float sW2[2 * CC * CC];
    __shared__ float sef[8][4][NBAS];
    __shared__ __align__(16) float sact[8][4][CC];
    for (int i = threadIdx.x; i < 2 * NBAS * CC; i += blockDim.x) sW1[i] = W1[i];
    for (int i = threadIdx.x; i < 2 * CC * CC; i += blockDim.x) sW2[i] = W2[i];
    __syncthreads();
    int warp = threadIdx.x >> 5, lane = threadIdx.x & 31;
    const float S3 = 1.7320508075688772f, S5 = 2.23606797749979f, S15 = 3.872983346207417f;
    for (int b = blockIdx.x * 8 + warp; b < EEDGE / 4; b += gridDim.x * 8) {
        int e0 = b * 4;
        if (lane < 4) {
            int e = e0 + lane;
            int snd = eidx[e], rcv = eidx[EEDGE + e];
            float vx = pos[snd * 3 + 0] - pos[rcv * 3 + 0] + shifts[e * 3 + 0];
            float vy = pos[snd * 3 + 1] - pos[rcv * 3 + 1] + shifts[e * 3 + 1];
            float vz = pos[snd * 3 + 2] - pos[rcv * 3 + 2] + shifts[e * 3 + 2];
            float r = sqrtf(vx * vx + vy * vy + vz * vz + 1e-12f);
            float inv = 1.0f / r;
            float x = vx * inv, y = vy * inv, z = vz * inv;
            float Yv[9];
            Yv[0] = 1.f; Yv[1] = S3 * x; Yv[2] = S3 * y; Yv[3] = S3 * z;
            Yv[4] = S15 * x * y; Yv[5] = S15 * y * z; Yv[6] = 0.5f * S5 * (3.f * z * z - 1.f);
            Yv[7] = S15 * x * z; Yv[8] = 0.5f * S15 * (x * x - y * y);
            float uu = r * (1.0f / RMAXF);
            float fc = 0.f;
            if (uu < 1.f) {
                float u2 = uu * uu, u4 = u2 * u2, u6 = u4 * u2, u7 = u6 * uu, u8 = u7 * uu;
                fc = 1.f - 28.f * u6 + 48.f * u7 - 21.f * u8;
            }
            const float A = 0.6324555320336759f;
            float th = r * (PI_F / RMAXF);
            float sb, cb;
            sincosf(th, &sb, &cb);
            float pref = A * inv * fc;
            float sn = sb, cn = cb;
            #pragma unroll
            for (int n = 0; n < NBAS; n++) {
                if (n > 0) {
                    float s2 = sn * cb + cn * sb;
                    float c2 = cn * cb - sn * sb;
                    sn = s2; cn = c2;
                }
                float efv = pref * sn;
                sef[warp][lane][n] = efv;
                d_ef[e * NBAS + n] = efv;
            }
            #pragma unroll
            for (int l = 0; l < 9; l++) d_Y[e * NL + l] = Yv[l];
            d_u3[e * 3 + 0] = x; d_u3[e * 3 + 1] = y; d_u3[e * 3 + 2] = z;
            d_r[e] = r;
        }
        __syncwarp();
        #pragma unroll
        for (int i = 0; i < 2; i++) {
            float z0[4] = {0.f, 0.f, 0.f, 0.f};
            float z1[4] = {0.f, 0.f, 0.f, 0.f};
            const float* w1 = &sW1[i * NBAS * CC];
            #pragma unroll
            for (int n = 0; n < NBAS; n++) {
                float wv0 = w1[n * CC + lane];
                float wv1 = w1[n * CC + lane + 32];
                #pragma unroll
                for (int e = 0; e < 4; e++) {
                    float efv = sef[warp][e][n];
                    z0[e] += efv * wv0;
                    z1[e] += efv * wv1;
                }
            }
            #pragma unroll
            for (int e = 0; e < 4; e++) {
                float sg0 = 1.f / (1.f + __expf(-z0[e]));
                float sg1 = 1.f / (1.f + __expf(-z1[e]));
                sact[warp][e][lane] = z0[e] * sg0;
                sact[warp][e][lane + 32] = z1[e] * sg1;
            }
            __syncwarp();
            float acc0[4] = {0.f, 0.f, 0.f, 0.f};
            float acc1[4] = {0.f, 0.f, 0.f, 0.f};
            const float* w2 = &sW2[i * CC * CC];
            #pragma unroll
            for (int c4 = 0; c4 < 16; c4++) {
                const float* w = &w2[c4 * 4 * CC + lane];
                float wA0 = w[0], wA1 = w[CC], wA2 = w[2 * CC], wA3 = w[3 * CC];
                float wB0 = w[32], wB1 = w[CC + 32], wB2 = w[2 * CC + 32], wB3 = w[3 * CC + 32];
                #pragma unroll
                for (int e = 0; e < 4; e++) {
                    float4 xv = ((const float4*)sact[warp][e])[c4];
                    acc0[e] += xv.x * wA0 + xv.y * wA1 + xv.z * wA2 + xv.w * wA3;
                    acc1[e] += xv.x * wB0 + xv.y * wB1 + xv.z * wB2 + xv.w * wB3;
                }
            }
            float* Rdst = i ? d_R1 : d_R0;
            #pragma unroll
            for (int e = 0; e < 4; e++) {
                int ee = e0 + e;
                Rdst[ee * CC + lane] = acc0[e];
                Rdst[ee * CC + lane + 32] = acc1[e];
            }
            __syncwarp();
        }
    }
}

// ---------------- K3: gather agg0 (rcv-CSR, 2x unrolled) + node update fused ----------------
__global__ void k_gather_upd(const float* __restrict__ attrs, const int* __restrict__ eidx,
                             const int* __restrict__ batch) {
    __shared__ float sWc[CC * CC];
    __shared__ float sku[NEL * CC];
    __shared__ float svr[CC];
    __shared__ float sskrd[NEL];
    __shared__ __align__(16) float scr[8][NL][CC];
    for (int i = threadIdx.x; i < CC * CC; i += blockDim.x) sWc[i] = d_Wc[i];
    for (int i = threadIdx.x; i < NEL * CC; i += blockDim.x) sku[i] = d_skup[i];
    for (int i = threadIdx.x; i < CC; i += blockDim.x) svr[i] = d_vread[i];
    if (threadIdx.x < NEL) sskrd[threadIdx.x] = d_skrd[threadIdx.x];
    __syncthreads();
    int warp = threadIdx.x >> 5, lane = threadIdx.x & 31;
    for (int n = blockIdx.x * 8 + warp; n < NNODE; n += gridDim.x * 8) {
        int beg = d_off_rcv[n], end = d_off_rcv[n + 1];
        float acc[NL][2];
        #pragma unroll
        for (int l = 0; l < NL; l++) { acc[l][0] = 0.f; acc[l][1] = 0.f; }
        int k = beg;
        for (; k + 1 < end; k += 2) {
            int ea = d_eid_rcv[k], eb = d_eid_rcv[k + 1];
            int sa = eidx[ea], sb = eidx[eb];
            float pa0 = d_R0[ea * CC + lane] * d_hu0[sa * CC + lane];
            float pa1 = d_R0[ea * CC + lane + 32] * d_hu0[sa * CC + lane + 32];
            float pb0 = d_R0[eb * CC + lane] * d_hu0[sb * CC + lane];
            float pb1 = d_R0[eb * CC + lane + 32] * d_hu0[sb * CC + lane + 32];
            #pragma unroll
            for (int l = 0; l < NL; l++) {
                float ya = d_Y[ea * NL + l], yb = d_Y[eb * NL + l];
                acc[l][0] += ya * pa0 + yb * pb0;
                acc[l][1] += ya * pa1 + yb * pb1;
            }
        }
        if (k < end) {
            int e = d_eid_rcv[k];
            int snd = eidx[e];
            float p0 = d_R0[e * CC + lane] * d_hu0[snd * CC + lane];
            float p1 = d_R0[e * CC + lane + 32] * d_hu0[snd * CC + lane + 32];
            #pragma unroll
            for (int l = 0; l < NL; l++) {
                float yl = d_Y[e * NL + l];
                acc[l][0] += yl * p0;
                acc[l][1] += yl * p1;
            }
        }
        float a0 = attrs[n * 4 + 0], a1 = attrs[n * 4 + 1], a2 = attrs[n * 4 + 2], a3 = attrs[n * 4 + 3];
        float ep = acc[0][0] * svr[lane] + acc[0][1] * svr[lane + 32];
        #pragma unroll
        for (int off = 16; off > 0; off >>= 1) ep += __shfl_xor_sync(0xffffffff, ep, off);
        if (lane == 0) {
            ep += a0 * sskrd[0] + a1 * sskrd[1] + a2 * sskrd[2] + a3 * sskrd[3];
            atomicAdd(&d_contrib[batch[n] * 3 + 1], ep);
        }
        #pragma unroll
        for (int l = 0; l < NL; l++) {
            scr[warp][l][lane] = acc[l][0];
            scr[warp][l][lane + 32] = acc[l][1];
        }
        __syncwarp();
        float o0[NL], o1[NL];
        #pragma unroll
        for (int l = 0; l < NL; l++) { o0[l] = 0.f; o1[l] = 0.f; }
        o0[0] = a0 * sku[lane] + a1 * sku[CC + lane] + a2 * sku[2 * CC + lane] + a3 * sku[3 * CC + lane];
        o1[0] = a0 * sku[lane + 32] + a1 * sku[CC + lane + 32] + a2 * sku[2 * CC + lane + 32] + a3 * sku[3 * CC + lane + 32];
        #pragma unroll
        for (int c4 = 0; c4 < 16; c4++) {
            const float* w = &sWc[(c4 * 4) * CC + lane];
            float wA0 = w[0], wA1 = w[CC], wA2 = w[2 * CC], wA3 = w[3 * CC];
            float wB0 = w[32], wB1 = w[CC + 32], wB2 = w[2 * CC + 32], wB3 = w[3 * CC + 32];
            #pragma unroll
            for (int l = 0; l < NL; l++) {
                float4 xv = ((const float4*)scr[warp][l])[c4];
                o0[l] += xv.x * wA0 + xv.y * wA1 + xv.z * wA2 + xv.w * wA3;
                o1[l] += xv.x * wB0 + xv.y * wB1 + xv.z * wB2 + xv.w * wB3;
            }
        }
        #pragma unroll
        for (int l = 0; l < NL; l++) {
            d_hu1[(n * NL + l) * CC + lane] = o0[l];
            d_hu1[(n * NL + l) * CC + lane + 32] = o1[l];
        }
        __syncwarp();
    }
}

// ---------------- K5: forward edge iter1 (warp-per-edge, scalar atomics) ----------------
__global__ void k_msg1(const int* __restrict__ eidx) {
    int warp = threadIdx.x >> 5, lane = threadIdx.x & 31;
    int e = blockIdx.x * 8 + warp;
    if (e >= EEDGE) return;
    int snd = eidx[e], rcv = eidx[EEDGE + e];
    float Yv[9];
    #pragma unroll
    for (int l = 0; l < 9; l++) Yv[l] = d_Y[e * NL + l];
    #pragma unroll
    for (int k = 0; k < 2; k++) {
        int c = lane + 32 * k;
        float s = 0.f;
        #pragma unroll
        for (int l = 0; l < 9; l++) s += d_hu1[(snd * NL + l) * CC + c] * Yv[l];
        atomicAdd(&d_agg1[rcv * CC + c], d_R1[e * CC + c] * s);
    }
}

// ---------------- K6: node2 (reads agg1) ----------------
__global__ void k_node2(const float* __restrict__ attrs, const float* __restrict__ W_out1,
                        const float* __restrict__ W_skip1, const float* __restrict__ W_r1,
                        const float* __restrict__ w_r2, const int* __restrict__ batch) {
    __shared__ float sWo[CC * CC];
    __shared__ float sWoT[CC * CC];
    __shared__ float sWr[CC * 17];
    __shared__ float sr2[HIDN];
    __shared__ float sSk[NEL * CC];
    __shared__ __align__(16) float scr[8][CC];
    __shared__ float sgz[8][HIDN];
    for (int i = threadIdx.x; i < CC * CC; i += blockDim.x) {
        sWo[i] = W_out1[i];
        int d = i / CC, c = i % CC;
        sWoT[i] = W_out1[c * CC + d];
    }
    for (int i = threadIdx.x; i < CC * HIDN; i += blockDim.x) {
        int c = i / HIDN, h = i % HIDN;
        sWr[c * 17 + h] = W_r1[i];
    }
    for (int i = threadIdx.x; i < HIDN; i += blockDim.x) sr2[i] = w_r2[i];
    for (int i = threadIdx.x; i < NEL * CC; i += blockDim.x) sSk[i] = W_skip1[i];
    __syncthreads();
    int warp = threadIdx.x >> 5, lane = threadIdx.x & 31;
    for (int n = blockIdx.x * 8 + warp; n < NNODE; n += gridDim.x * 8) {
        float4* s4 = (float4*)scr[warp];
        if (lane < 16) s4[lane] = ((const float4*)&d_agg1[n * CC])[lane];
        __syncwarp();
        float a0 = attrs[n * 4 + 0], a1 = attrs[n * 4 + 1], a2 = attrs[n * 4 + 2], a3 = attrs[n * 4 + 3];
        float h2a, h2b;
        {
            float acc0 = a0 * sSk[lane] + a1 * sSk[CC + lane] + a2 * sSk[2 * CC + lane] + a3 * sSk[3 * CC + lane];
            float acc1 = a0 * sSk[lane + 32] + a1 * sSk[CC + lane + 32] + a2 * sSk[2 * CC + lane + 32] + a3 * sSk[3 * CC + lane + 32];
            const float4* x4 = (const float4*)scr[warp];
            #pragma unroll
            for (int c4 = 0; c4 < 16; c4++) {
                float4 xv = x4[c4];
                const float* w = &sWo[(c4 * 4) * CC + lane];
                acc0 += xv.x * w[0] + xv.y * w[CC] + xv.z * w[2 * CC] + xv.w * w[3 * CC];
                acc1 += xv.x * w[32] + xv.y * w[CC + 32] + xv.z * w[2 * CC + 32] + xv.w * w[3 * CC + 32];
            }
            h2a = acc0; h2b = acc1;
        }
        __syncwarp();
        scr[warp][lane] = h2a; scr[warp][lane + 32] = h2b;
        __syncwarp();
        float ep = 0.f;
        if (lane < HIDN) {
            float zv = 0.f;
            #pragma unroll 8
            for (int d = 0; d < CC; d++) zv += scr[warp][d] * sWr[d * 17 + lane];
            float sg = 1.f / (1.f + __expf(-zv));
            ep = zv * sg * sr2[lane];
            sgz[warp][lane] = sg * (1.f + zv * (1.f - sg)) * sr2[lane];
        }
        #pragma unroll
        for (int off = 16; off > 0; off >>= 1) ep += __shfl_xor_sync(0xffffffff, ep, off);
        if (lane == 0) atomicAdd(&d_contrib[batch[n] * 3 + 2], ep);
        __syncwarp();
        float gh2a = 0.f, gh2b = 0.f;
        #pragma unroll
        for (int h = 0; h < HIDN; h++) {
            float g = sgz[warp][h];
            gh2a += g * sWr[lane * 17 + h];
            gh2b += g * sWr[(lane + 32) * 17 + h];
        }
        __syncwarp();
        scr[warp][lane] = gh2a; scr[warp][lane + 32] = gh2b;
        __syncwarp();
        {
            const float4* x4 = (const float4*)scr[warp];
            float acc0 = 0.f, acc1 = 0.f;
            #pragma unroll
            for (int c4 = 0; c4 < 16; c4++) {
                float4 xv = x4[c4];
                const float* w = &sWoT[(c4 * 4) * CC + lane];
                acc0 += xv.x * w[0] + xv.y * w[CC] + xv.z * w[2 * CC] + xv.w * w[3 * CC];
                acc1 += xv.x * w[32] + xv.y * w[CC + 32] + xv.z * w[2 * CC + 32] + xv.w * w[3 * CC + 32];
            }
            d_gagg1[n * CC + lane] = acc0;
            d_gagg1[n * CC + lane + 32] = acc1;
        }
        __syncwarp();
    }
}

// ---------------- K7: gather gagg0 (snd-CSR, 2x unrolled) + backward node fused ----------------
__global__ void k_back_gather(const int* __restrict__ eidx) {
    __shared__ float sWcT[CC * CC];
    __shared__ float svr[CC];
    __shared__ __align__(16) float scr[8][NL][CC];
    for (int i = threadIdx.x; i < CC * CC; i += blockDim.x) sWcT[i] = d_WcT[i];
    for (int i = threadIdx.x; i < CC; i += blockDim.x) svr[i] = d_vread[i];
    __syncthreads();
    int warp = threadIdx.x >> 5, lane = threadIdx.x & 31;
    for (int n = blockIdx.x * 8 + warp; n < NNODE; n += gridDim.x * 8) {
        int beg = d_off_snd[n], end = d_off_snd[n + 1];
        float acc[NL][2];
        #pragma unroll
        for (int l = 0; l < NL; l++) { acc[l][0] = 0.f; acc[l][1] = 0.f; }
        int k = beg;
        for (; k + 1 < end; k += 2) {
            int ea = d_eid_snd[k], eb = d_eid_snd[k + 1];
            int ra = eidx[EEDGE + ea], rb = eidx[EEDGE + eb];
            float qa0 = d_R1[ea * CC + lane] * d_gagg1[ra * CC + lane];
            float qa1 = d_R1[ea * CC + lane + 32] * d_gagg1[ra * CC + lane + 32];
            float qb0 = d_R1[eb * CC + lane] * d_gagg1[rb * CC + lane];
            float qb1 = d_R1[eb * CC + lane + 32] * d_gagg1[rb * CC + lane + 32];
            #pragma unroll
            for (int l = 0; l < NL; l++) {
                float ya = d_Y[ea * NL + l], yb = d_Y[eb * NL + l];
                acc[l][0] += ya * qa0 + yb * qb0;
                acc[l][1] += ya * qa1 + yb * qb1;
            }
        }
        if (k < end) {
            int e = d_eid_snd[k];
            int rcv = eidx[EEDGE + e];
            float q0 = d_R1[e * CC + lane] * d_gagg1[rcv * CC + lane];
            float q1 = d_R1[e * CC + lane + 32] * d_gagg1[rcv * CC + lane + 32];
            #pragma unroll
            for (int l = 0; l < NL; l++) {
                float yl = d_Y[e * NL + l];
                acc[l][0] += yl * q0;
                acc[l][1] += yl * q1;
            }
        }
        #pragma unroll
        for (int l = 0; l < NL; l++) {
            scr[warp][l][lane] = acc[l][0];
            scr[warp][l][lane + 32] = acc[l][1];
        }
        __syncwarp();
        float o0[NL], o1[NL];
        #pragma unroll
        for (int l = 0; l < NL; l++) { o0[l] = 0.f; o1[l] = 0.f; }
        o0[0] = svr[lane];
        o1[0] = svr[lane + 32];
        #pragma unroll
        for (int c4 = 0; c4 < 16; c4++) {
            const float* w = &sWcT[(c4 * 4) * CC + lane];
            float wA0 = w[0], wA1 = w[CC], wA2 = w[2 * CC], wA3 = w[3 * CC];
            float wB0 = w[32], wB1 = w[CC + 32], wB2 = w[2 * CC + 32], wB3 = w[3 * CC + 32];
            #pragma unroll
            for (int l = 0; l < NL; l++) {
                float4 xv = ((const float4*)scr[warp][l])[c4];
                o0[l] += xv.x * wA0 + xv.y * wA1 + xv.z * wA2 + xv.w * wA3;
                o1[l] += xv.x * wB0 + xv.y * wB1 + xv.z * wB2 + xv.w * wB3;
            }
        }
        #pragma unroll
        for (int l = 0; l < NL; l++) {
            d_gagg0[(n * NL + l) * CC + lane] = o0[l];
            d_gagg0[(n * NL + l) * CC + lane + 32] = o1[l];
        }
        __syncwarp();
    }
}

// ---------------- K9: backward edges -> forces, 4-edge batched ----------------
__global__ void __launch_bounds__(256, 2)
k_back_edge(const int* __restrict__ eidx,
            const float* __restrict__ W1, const float* __restrict__ W2,
            float* __restrict__ force) {
    __shared__ float sW2T[2][CC * CC];
    __shared__ float sW1p[2][NBAS * 65];
    __shared__ __align__(16) float sAB[8][4][CC];
    __shared__ float sef[8][4][NBAS];
    __shared__ float sgeo[8][4][4];
    for (int i = threadIdx.x; i < 2 * CC * CC; i += blockDim.x) {
        int w = i / (CC * CC), rem = i % (CC * CC);
        int c = rem / CC, j = rem % CC;
        sW2T[w][rem] = W2[w * CC * CC + j * CC + c];
    }
    for (int i = threadIdx.x; i < 2 * NBAS * CC; i += blockDim.x) {
        int w = i / (NBAS * CC), rem = i % (NBAS * CC);
        int n = rem / CC, j = rem % CC;
        sW1p[w][n * 65 + j] = W1[i];
    }
    __syncthreads();
    int warp = threadIdx.x >> 5, lane = threadIdx.x & 31;
    const float S3 = 1.7320508075688772f, S5 = 2.23606797749979f, S15 = 3.872983346207417f;
    for (int b = blockIdx.x * 8 + warp; b < EEDGE / 4; b += gridDim.x * 8) {
        int e0 = b * 4;
        float pX[4], pY[4], pZ[4];
        float gR1a[4], gR1b[4];
        int snds[4], rcvs[4];
        #pragma unroll
        for (int e = 0; e < 4; e++) {
            int ee = e0 + e;
            int snd = eidx[ee], rcv = eidx[EEDGE + ee];
            snds[e] = snd; rcvs[e] = rcv;
            float Yv[9];
            #pragma unroll
            for (int l = 0; l < 9; l++) Yv[l] = d_Y[ee * NL + l];
            float ux = d_u3[ee * 3], uy = d_u3[ee * 3 + 1], uz = d_u3[ee * 3 + 2];
            if (lane == 0) {
                sgeo[warp][e][0] = ux; sgeo[warp][e][1] = uy; sgeo[warp][e][2] = uz;
                sgeo[warp][e][3] = d_r[ee];
            }
            if (lane < NBAS) sef[warp][e][lane] = d_ef[ee * NBAS + lane];
            float cx[9] = {0.f, S3, 0.f, 0.f, S15 * uy, 0.f, 0.f, S15 * uz, S15 * ux};
            float cy[9] = {0.f, 0.f, S3, 0.f, S15 * ux, S15 * uz, 0.f, 0.f, -S15 * uy};
            float cz[9] = {0.f, 0.f, 0.f, S3, 0.f, S15 * uy, 3.f * S5 * uz, S15 * ux, 0.f};
            float g0 = d_gagg1[rcv * CC + lane], g1 = d_gagg1[rcv * CC + lane + 32];
            float R1a = d_R1[ee * CC + lane], R1b = d_R1[ee * CC + lane + 32];
            float gs1a = R1a * g0, gs1b = R1b * g1;
            float s0a = d_hu0[snd * CC + lane], s0b = d_hu0[snd * CC + lane + 32];
            float p0a = d_R0[ee * CC + lane] * s0a, p0b = d_R0[ee * CC + lane + 32] * s0b;
            float t0a = 0.f, t0b = 0.f, s1a = 0.f, s1b = 0.f;
            float px = 0.f, py = 0.f, pz = 0.f;
            #pragma unroll
            for (int l = 0; l < 9; l++) {
                float ga = d_gagg0[(rcv * NL + l) * CC + lane];
                float gb = d_gagg0[(rcv * NL + l) * CC + lane + 32];
                float ha = d_hu1[(snd * NL + l) * CC + lane];
                float hb = d_hu1[(snd * NL + l) * CC + lane + 32];
                t0a += Yv[l] * ga; t0b += Yv[l] * gb;
                s1a += ha * Yv[l]; s1b += hb * Yv[l];
                if (l > 0) {
                    float part = p0a * ga + p0b * gb + ha * gs1a + hb * gs1b;
                    px += cx[l] * part;
                    py += cy[l] * part;
                    pz += cz[l] * part;
                }
            }
            sAB[warp][e][lane] = t0a * s0a;
            sAB[warp][e][lane + 32] = t0b * s0b;
            gR1a[e] = s1a * g0; gR1b[e] = s1b * g1;
            pX[e] = px; pY[e] = py; pZ[e] = pz;
        }
        __syncwarp();
        float gefl = 0.f;
        int eg = lane >> 3, nb = lane & 7;
        #pragma unroll
        for (int i = 0; i < 2; i++) {
            if (i == 1) {
                __syncwarp();
                #pragma unroll
                for (int e = 0; e < 4; e++) {
                    sAB[warp][e][lane] = gR1a[e];
                    sAB[warp][e][lane + 32] = gR1b[e];
                }
                __syncwarp();
            }
            float gz0[4] = {0.f, 0.f, 0.f, 0.f};
            float gz1[4] = {0.f, 0.f, 0.f, 0.f};
            #pragma unroll
            for (int c4 = 0; c4 < 16; c4++) {
                const float* w = &sW2T[i][(c4 * 4) * CC + lane];
                float wA0 = w[0], wA1 = w[CC], wA2 = w[2 * CC], wA3 = w[3 * CC];
                float wB0 = w[32], wB1 = w[CC + 32], wB2 = w[2 * CC + 32], wB3 = w[3 * CC + 32];
                #pragma unroll
                for (int e = 0; e < 4; e++) {
                    float4 xv = ((const float4*)sAB[warp][e])[c4];
                    gz0[e] += xv.x * wA0 + xv.y * wA1 + xv.z * wA2 + xv.w * wA3;
                    gz1[e] += xv.x * wB0 + xv.y * wB1 + xv.z * wB2 + xv.w * wB3;
                }
            }
            float pre0[4] = {0.f, 0.f, 0.f, 0.f};
            float pre1[4] = {0.f, 0.f, 0.f, 0.f};
            #pragma unroll
            for (int n = 0; n < NBAS; n++) {
                float wv0 = sW1p[i][n * 65 + lane];
                float wv1 = sW1p[i][n * 65 + lane + 32];
                #pragma unroll
                for (int e = 0; e < 4; e++) {
                    float efv = sef[warp][e][n];
                    pre0[e] += efv * wv0;
                    pre1[e] += efv * wv1;
                }
            }
            __syncwarp();
            #pragma unroll
            for (int e = 0; e < 4; e++) {
                float sg0 = 1.f / (1.f + __expf(-pre0[e]));
                float sg1 = 1.f / (1.f + __expf(-pre1[e]));
                sAB[warp][e][lane] = gz0[e] * sg0 * (1.f + pre0[e] * (1.f - sg0));
                sAB[warp][e][lane + 32] = gz1[e] * sg1 * (1.f + pre1[e] * (1.f - sg1));
            }
            __syncwarp();
            float acc = 0.f;
            #pragma unroll 8
            for (int j = 0; j < CC; j++)
                acc += sAB[warp][eg][j] * sW1p[i][nb * 65 + j];
            gefl += acc;
        }
        float grp;
        {
            float r_e = sgeo[warp][eg][3];
            float kn = (nb + 1) * (PI_F / RMAXF);
            float invr = 1.f / r_e;
            const float A = 0.6324555320336759f;
            float sn, cs;
            sincosf(kn * r_e, &sn, &cs);
            float uu = r_e * (1.0f / RMAXF);
            float fc = 0.f, dfc = 0.f;
            if (uu < 1.f) {
                float u2 = uu * uu, u4 = u2 * u2, u5 = u4 * uu, u6 = u5 * uu, u7 = u6 * uu;
                fc = 1.f - 28.f * u6 + 48.f * u7 - 21.f * u7 * uu;
                dfc = (-168.f * u5 + 336.f * u6 - 168.f * u7) * (1.0f / RMAXF);
            }
            float rb = A * sn * invr;
            float drb = A * (kn * cs - sn * invr) * invr;
            grp = gefl * (drb * fc + rb * dfc);
        }
        #pragma unroll
        for (int off = 4; off > 0; off >>= 1) grp += __shfl_xor_sync(0xffffffff, grp, off);
        #pragma unroll
        for (int e = 0; e < 4; e++) {
            #pragma unroll
            for (int off = 16; off > 0; off >>= 1) {
                pX[e] += __shfl_xor_sync(0xffffffff, pX[e], off);
                pY[e] += __shfl_xor_sync(0xffffffff, pY[e], off);
                pZ[e] += __shfl_xor_sync(0xffffffff, pZ[e], off);
            }
        }
        if ((lane & 7) == 0) {
            int e = eg;
            float px = (e == 0) ? pX[0] : (e == 1) ? pX[1] : (e == 2) ? pX[2] : pX[3];
            float py = (e == 0) ? pY[0] : (e == 1) ? pY[1] : (e == 2) ? pY[2] : pY[3];
            float pz = (e == 0) ? pZ[0] : (e == 1) ? pZ[1] : (e == 2) ? pZ[2] : pZ[3];
            int snd = (e == 0) ? snds[0] : (e == 1) ? snds[1] : (e == 2) ? snds[2] : snds[3];
            int rcv = (e == 0) ? rcvs[0] : (e == 1) ? rcvs[1] : (e == 2) ? rcvs[2] : rcvs[3];
            float ux = sgeo[warp][e][0], uy = sgeo[warp][e][1], uz = sgeo[warp][e][2];
            float invr = 1.f / sgeo[warp][e][3];
            if (snd != rcv) {
                float dot = px * ux + py * uy + pz * uz;
                float gvx = (px - dot * ux) * invr + grp * ux;
                float gvy = (py - dot * uy) * invr + grp * uy;
                float gvz = (pz - dot * uz) * invr + grp * uz;
                atomicAdd(&force[snd * 3 + 0], -gvx);
                atomicAdd(&force[snd * 3 + 1], -gvy);
                atomicAdd(&force[snd * 3 + 2], -gvz);
                atomicAdd(&force[rcv * 3 + 0], gvx);
                atomicAdd(&force[rcv * 3 + 1], gvy);
                atomicAdd(&force[rcv * 3 + 2], gvz);
            }
        }
    }
}

// ---------------- K10: finalize ----------------
__global__ void k_final(float* __restrict__ out) {
    int g = threadIdx.x;
    if (g < GG) {
        float c0 = d_contrib[g * 3 + 0], c1 = d_contrib[g * 3 + 1], c2 = d_contrib[g * 3 + 2];
        out[g] = c0 + c1 + c2;
        out[GG + g * 3 + 0] = c0;
        out[GG + g * 3 + 1] = c1;
        out[GG + g * 3 + 2] = c2;
    }
}

extern "C" void kernel_launch(void* const* d_in, const int* in_sizes, int n_in,
                              void* d_out, int out_size) {
    const float* pos     = (const float*)d_in[0];
    const float* attrs   = (const float*)d_in[1];
    const float* shifts  = (const float*)d_in[2];
    const float* ae      = (const float*)d_in[3];
    const float* W_embed = (const float*)d_in[4];
    const float* W_up    = (const float*)d_in[5];
    const float* W1      = (const float*)d_in[6];
    const float* W2      = (const float*)d_in[7];
    const float* W_out   = (const float*)d_in[8];
    const float* W_skip  = (const float*)d_in[9];
    const float* w_read0 = (const float*)d_in[10];
    const float* W_r1    = (const float*)d_in[11];
    const float* w_r2    = (const float*)d_in[12];
    const int*   eidx    = (const int*)d_in[13];
    const int*   batch   = (const int*)d_in[14];
    float* out = (float*)d_out;

    k_zero<<<(NNODE * CC / 4 + 255) / 256, 256>>>(out, out_size);
    k_pre<<<1, 256>>>(W_embed, W_up, W_out, W_skip, w_read0);
    k_hist<<<(EEDGE + 255) / 256, 256>>>(eidx);
    k_scan2<<<2, 1024>>>();
    k_fill<<<(EEDGE + 255) / 256, 256>>>(eidx);
    k_node_init<<<(NNODE + 7) / 8, 256>>>(attrs, ae, batch);
    k_edge_fwd<<<EBLK, 256>>>(pos, shifts, eidx, W1, W2);
    k_gather_upd<<<NBLK, 256>>>(attrs, eidx, batch);
    k_msg1<<<(EEDGE + 7) / 8, 256>>>(eidx);
    k_node2<<<NBLK, 256>>>(attrs, W_out + CC * CC, W_skip + NEL * CC, W_r1, w_r2, batch);
    k_back_gather<<<NBLK, 256>>>(eidx);
    k_back_edge<<<NBLK, 256>>>(eidx, W1, W2, out + GG + GG * 3);
    k_final<<<1, 64>>>(out);
}